// round 2
// baseline (speedup 1.0000x reference)
#include <cuda_runtime.h>
#include <math.h>

#define Bc 8
#define Lc 1024
#define Dc 256
#define Hc 8
#define HDc 32
#define Mc (Bc*Lc)   // 8192

typedef unsigned long long ull;

// Scratch (allocation-free: __device__ globals)
__device__ float g_k[Mc*Dc];
__device__ float g_v[Mc*Dc];
__device__ float g_q[Mc*Dc];
__device__ float g_sk[Mc*Dc];
__device__ float g_sv[Mc*Dc];
__device__ float g_y[Mc*Dc];
__device__ unsigned g_mb[Bc*Lc*Lc/32];   // packed mask bits, 1MB

// ---- packed fp32 helpers (sm_103a f32x2 pipe) --------------------------------
__device__ __forceinline__ ull pk2(float x, float y) {
    ull r; asm("mov.b64 %0,{%1,%2};" : "=l"(r) : "f"(x), "f"(y)); return r;
}
__device__ __forceinline__ void upk2(ull v, float& x, float& y) {
    asm("mov.b64 {%0,%1},%2;" : "=f"(x), "=f"(y) : "l"(v));
}
__device__ __forceinline__ void ffma2(ull& d, ull a, ull b) {
    asm("fma.rn.f32x2 %0,%1,%2,%0;" : "+l"(d) : "l"(a), "l"(b));
}
__device__ __forceinline__ void fmul2(ull& d, ull a, ull b) {
    asm("mul.rn.f32x2 %0,%1,%2;" : "=l"(d) : "l"(a), "l"(b));
}
__device__ __forceinline__ float hadd2(ull a) {
    float x, y; upk2(a, x, y); return x + y;
}

// ---------------------------------------------------------------------------
// Mask pack: one bit per (b,l,j). Coalesced read, ballot, one word per warp.
// ---------------------------------------------------------------------------
__global__ __launch_bounds__(256)
void pack_mask_kernel(const int* __restrict__ mask, unsigned* __restrict__ mb)
{
    int i = blockIdx.x * 256 + threadIdx.x;
    unsigned bits = __ballot_sync(0xffffffffu, mask[i] != 0);
    if ((threadIdx.x & 31) == 0) mb[i >> 5] = bits;
}

// ---------------------------------------------------------------------------
// GEMM: C[M,N] = A[M,K] @ W[K,N] + bias. Tile 128x128x16, 256 thr, 8x8 micro.
// FFMA2 with W pre-duplicated in smem (zero pack instrs in mainloop).
// ---------------------------------------------------------------------------
__global__ __launch_bounds__(256)
void gemm_bias_kernel(const float* __restrict__ A0,
                      const float* __restrict__ A1,
                      int K0, int K,
                      const float* __restrict__ W,
                      const float* __restrict__ bias,
                      float* __restrict__ C, int N)
{
    __shared__ float As[16][132];     // [k][m], padded
    __shared__ ull   Ws2[16][128];    // [k][n], each entry = (w,w)

    const int tid = threadIdx.x;
    const int tx = tid & 15;
    const int ty = tid >> 4;
    const int m0 = blockIdx.y * 128;
    const int n0 = blockIdx.x * 128;
    const int K1 = K - K0;

    ull acc[4][8];
    #pragma unroll
    for (int i = 0; i < 4; i++)
        #pragma unroll
        for (int j = 0; j < 8; j++) acc[i][j] = 0ull;

    for (int k0 = 0; k0 < K; k0 += 16) {
        __syncthreads();
        // A tile 128x16, transposed store (m contiguous in smem)
        #pragma unroll
        for (int it = 0; it < 2; it++) {
            int idx = tid + it * 256;
            int m = idx >> 2, kq = (idx & 3) * 4;
            int gk = k0 + kq;
            float4 av;
            if (gk < K0) av = *(const float4*)&A0[(size_t)(m0 + m) * K0 + gk];
            else         av = *(const float4*)&A1[(size_t)(m0 + m) * K1 + gk - K0];
            As[kq + 0][m] = av.x; As[kq + 1][m] = av.y;
            As[kq + 2][m] = av.z; As[kq + 3][m] = av.w;
        }
        // W tile 16x128, duplicated entries
        #pragma unroll
        for (int it = 0; it < 2; it++) {
            int idx = tid + it * 256;
            int kk = idx >> 5, n = (idx & 31) * 4;
            float4 wv = *(const float4*)&W[(size_t)(k0 + kk) * N + n0 + n];
            Ws2[kk][n + 0] = pk2(wv.x, wv.x);
            Ws2[kk][n + 1] = pk2(wv.y, wv.y);
            Ws2[kk][n + 2] = pk2(wv.z, wv.z);
            Ws2[kk][n + 3] = pk2(wv.w, wv.w);
        }
        __syncthreads();
        #pragma unroll
        for (int kk = 0; kk < 16; kk++) {
            ulonglong2 a01 = *(const ulonglong2*)&As[kk][ty * 8];
            ulonglong2 a23 = *(const ulonglong2*)&As[kk][ty * 8 + 4];
            ull a2[4] = {a01.x, a01.y, a23.x, a23.y};
            ulonglong2 w01 = *(const ulonglong2*)&Ws2[kk][tx * 8 + 0];
            ulonglong2 w23 = *(const ulonglong2*)&Ws2[kk][tx * 8 + 2];
            ulonglong2 w45 = *(const ulonglong2*)&Ws2[kk][tx * 8 + 4];
            ulonglong2 w67 = *(const ulonglong2*)&Ws2[kk][tx * 8 + 6];
            ull w2[8] = {w01.x, w01.y, w23.x, w23.y, w45.x, w45.y, w67.x, w67.y};
            #pragma unroll
            for (int mp = 0; mp < 4; mp++)
                #pragma unroll
                for (int j = 0; j < 8; j++)
                    ffma2(acc[mp][j], a2[mp], w2[j]);
        }
    }

    // Epilogue
    float bcol[8];
    #pragma unroll
    for (int j = 0; j < 8; j++) bcol[j] = bias[n0 + tx * 8 + j];
    #pragma unroll
    for (int mp = 0; mp < 4; mp++) {
        float r0[8], r1[8];
        #pragma unroll
        for (int j = 0; j < 8; j++) {
            upk2(acc[mp][j], r0[j], r1[j]);
            r0[j] += bcol[j]; r1[j] += bcol[j];
        }
        int mA = m0 + ty * 8 + mp * 2;
        float* c0 = &C[(size_t)mA * N + n0 + tx * 8];
        float* c1 = c0 + N;
        *(float4*)&c0[0] = make_float4(r0[0], r0[1], r0[2], r0[3]);
        *(float4*)&c0[4] = make_float4(r0[4], r0[5], r0[6], r0[7]);
        *(float4*)&c1[0] = make_float4(r1[0], r1[1], r1[2], r1[3]);
        *(float4*)&c1[4] = make_float4(r1[4], r1[5], r1[6], r1[7]);
    }
}

// ---------------------------------------------------------------------------
// Attention: 256 threads, 2 query rows per thread (512 rows/block).
// Online softmax, FFMA2 throughout, K/V tiles read as ulonglong2.
// Diagonal term seeds the online state (value = self_v); j==l skipped.
// ---------------------------------------------------------------------------
__global__ __launch_bounds__(256)
void attn_kernel(const float* __restrict__ q,
                 const float* __restrict__ k,
                 const float* __restrict__ v,
                 const float* __restrict__ sk,
                 const float* __restrict__ sv,
                 const unsigned* __restrict__ mb,
                 float* __restrict__ y)
{
    __shared__ float Ks[128][HDc];
    __shared__ float Vs[128][HDc];

    const int bh = blockIdx.y;
    const int b = bh >> 3, h = bh & 7;
    const int l0 = blockIdx.x * 512;
    const int tid = threadIdx.x;
    const int la = l0 + tid;
    const int lb = la + 256;
    const int rowa = (b * Lc + la) * Dc + h * HDc;
    const int rowb = (b * Lc + lb) * Dc + h * HDc;
    const float scale = 0.17677669529663687f;   // 1/sqrt(32)
    const float NEG_INF = __int_as_float(0xff800000);
    const ull sc2 = pk2(scale, scale);

    // q (pre-scaled), as packed pairs
    ull qa[16], qb[16];
    #pragma unroll
    for (int i = 0; i < 8; i++) {
        ulonglong2 ta = *(const ulonglong2*)&q[rowa + i * 4];
        ulonglong2 tb = *(const ulonglong2*)&q[rowb + i * 4];
        fmul2(qa[2 * i], ta.x, sc2); fmul2(qa[2 * i + 1], ta.y, sc2);
        fmul2(qb[2 * i], tb.x, sc2); fmul2(qb[2 * i + 1], tb.y, sc2);
    }

    // diagonal scores
    ull da0 = 0, da1 = 0, db0 = 0, db1 = 0;
    #pragma unroll
    for (int i = 0; i < 8; i++) {
        ulonglong2 ka = *(const ulonglong2*)&sk[rowa + i * 4];
        ulonglong2 kb = *(const ulonglong2*)&sk[rowb + i * 4];
        ffma2(da0, qa[2 * i], ka.x); ffma2(da1, qa[2 * i + 1], ka.y);
        ffma2(db0, qb[2 * i], kb.x); ffma2(db1, qb[2 * i + 1], kb.y);
    }
    float swa = hadd2(da0) + hadd2(da1);
    float swb = hadd2(db0) + hadd2(db1);

    float ma = NEG_INF, suma = 0.f, mB = NEG_INF, sumb = 0.f;
    ull acca[16], accb[16];
    #pragma unroll
    for (int i = 0; i < 16; i++) { acca[i] = 0ull; accb[i] = 0ull; }

    {   // seed with diagonal term if mask diag set
        unsigned wa = mb[(unsigned)((b * Lc + la) * Lc + la) >> 5];
        unsigned wb = mb[(unsigned)((b * Lc + lb) * Lc + lb) >> 5];
        if ((wa >> (la & 31)) & 1u) {
            ma = swa; suma = 1.f;
            #pragma unroll
            for (int i = 0; i < 8; i++) {
                ulonglong2 t = *(const ulonglong2*)&sv[rowa + i * 4];
                acca[2 * i] = t.x; acca[2 * i + 1] = t.y;
            }
        }
        if ((wb >> (lb & 31)) & 1u) {
            mB = swb; sumb = 1.f;
            #pragma unroll
            for (int i = 0; i < 8; i++) {
                ulonglong2 t = *(const ulonglong2*)&sv[rowb + i * 4];
                accb[2 * i] = t.x; accb[2 * i + 1] = t.y;
            }
        }
    }

    const unsigned wbase_a = (unsigned)((b * Lc + la) * Lc) >> 5;
    const unsigned wbase_b = (unsigned)((b * Lc + lb) * Lc) >> 5;

    for (int j0 = 0; j0 < Lc; j0 += 128) {
        __syncthreads();
        #pragma unroll
        for (int it = 0; it < 4; it++) {
            int idx = tid + it * 256;
            int jj = idx >> 3, dd = (idx & 7) * 4;
            int g = (b * Lc + j0 + jj) * Dc + h * HDc + dd;
            *(float4*)&Ks[jj][dd] = *(const float4*)&k[g];
            *(float4*)&Vs[jj][dd] = *(const float4*)&v[g];
        }
        __syncthreads();

        unsigned mwa[4], mwb[4];
        #pragma unroll
        for (int w = 0; w < 4; w++) {
            mwa[w] = mb[wbase_a + (j0 >> 5) + w];
            mwb[w] = mb[wbase_b + (j0 >> 5) + w];
        }

        for (int jj = 0; jj < 128; jj++) {
            int j = j0 + jj;
            ull d0 = 0, d1 = 0, e0 = 0, e1 = 0;
            #pragma unroll
            for (int i = 0; i < 4; i++) {
                ulonglong2 k01 = *(const ulonglong2*)&Ks[jj][i * 8];
                ulonglong2 k23 = *(const ulonglong2*)&Ks[jj][i * 8 + 4];
                ffma2(d0, qa[i * 4 + 0], k01.x); ffma2(d1, qa[i * 4 + 1], k01.y);
                ffma2(d0, qa[i * 4 + 2], k23.x); ffma2(d1, qa[i * 4 + 3], k23.y);
                ffma2(e0, qb[i * 4 + 0], k01.x); ffma2(e1, qb[i * 4 + 1], k01.y);
                ffma2(e0, qb[i * 4 + 2], k23.x); ffma2(e1, qb[i * 4 + 3], k23.y);
            }
            float sa = hadd2(d0) + hadd2(d1);
            float sb = hadd2(e0) + hadd2(e1);

            bool ua = (((mwa[jj >> 5] >> (jj & 31)) & 1u) != 0u) && (j != la);
            bool ub = (((mwb[jj >> 5] >> (jj & 31)) & 1u) != 0u) && (j != lb);

            if (ua) {
                if (sa > ma) {
                    float corr = __expf(ma - sa);
                    ull c2 = pk2(corr, corr);
                    suma *= corr;
                    #pragma unroll
                    for (int i = 0; i < 16; i++) fmul2(acca[i], acca[i], c2);
                    ma = sa;
                }
                float p = __expf(sa - ma);
                suma += p;
                ull p2 = pk2(p, p);
                #pragma unroll
                for (int i = 0; i < 8; i++) {
                    ulonglong2 vv = *(const ulonglong2*)&Vs[jj][i * 4];
                    ffma2(acca[2 * i], p2, vv.x);
                    ffma2(acca[2 * i + 1], p2, vv.y);
                }
            }
            if (ub) {
                if (sb > mB) {
                    float corr = __expf(mB - sb);
                    ull c2 = pk2(corr, corr);
                    sumb *= corr;
                    #pragma unroll
                    for (int i = 0; i < 16; i++) fmul2(accb[i], accb[i], c2);
                    mB = sb;
                }
                float p = __expf(sb - mB);
                sumb += p;
                ull p2 = pk2(p, p);
                #pragma unroll
                for (int i = 0; i < 8; i++) {
                    ulonglong2 vv = *(const ulonglong2*)&Vs[jj][i * 4];
                    ffma2(accb[2 * i], p2, vv.x);
                    ffma2(accb[2 * i + 1], p2, vv.y);
                }
            }
        }
    }

    float inva = (suma > 0.f) ? (1.f / suma) : 0.f;
    float invb = (sumb > 0.f) ? (1.f / sumb) : 0.f;
    float oa[32], ob[32];
    #pragma unroll
    for (int p = 0; p < 16; p++) {
        upk2(acca[p], oa[2 * p], oa[2 * p + 1]);
        upk2(accb[p], ob[2 * p], ob[2 * p + 1]);
    }
    #pragma unroll
    for (int i = 0; i < 8; i++) {
        *(float4*)&y[rowa + i * 4] = make_float4(oa[4*i]*inva, oa[4*i+1]*inva,
                                                 oa[4*i+2]*inva, oa[4*i+3]*inva);
        *(float4*)&y[rowb + i * 4] = make_float4(ob[4*i]*invb, ob[4*i+1]*invb,
                                                 ob[4*i+2]*invb, ob[4*i+3]*invb);
    }
}

// ---------------------------------------------------------------------------
extern "C" void kernel_launch(void* const* d_in, const int* in_sizes, int n_in,
                              void* d_out, int out_size)
{
    const float* obs = (const float*)d_in[0];
    const float* act = (const float*)d_in[1];
    const int*   msk = (const int*)  d_in[2];
    const float* Wk  = (const float*)d_in[3];
    const float* bk  = (const float*)d_in[4];
    const float* Wv  = (const float*)d_in[5];
    const float* bv  = (const float*)d_in[6];
    const float* Wq  = (const float*)d_in[7];
    const float* bq  = (const float*)d_in[8];
    const float* Wks = (const float*)d_in[9];
    const float* bks = (const float*)d_in[10];
    const float* Wvs = (const float*)d_in[11];
    const float* bvs = (const float*)d_in[12];
    const float* Wp  = (const float*)d_in[13];
    const float* bp  = (const float*)d_in[14];
    float* out = (float*)d_out;

    float *pk, *pv, *pq, *psk, *psv, *py;
    unsigned* pmb;
    cudaGetSymbolAddress((void**)&pk,  g_k);
    cudaGetSymbolAddress((void**)&pv,  g_v);
    cudaGetSymbolAddress((void**)&pq,  g_q);
    cudaGetSymbolAddress((void**)&psk, g_sk);
    cudaGetSymbolAddress((void**)&psv, g_sv);
    cudaGetSymbolAddress((void**)&py,  g_y);
    cudaGetSymbolAddress((void**)&pmb, g_mb);

    // mask pack (1 bit per entry)
    pack_mask_kernel<<<(Bc*Lc*Lc)/256, 256>>>(msk, pmb);

    dim3 gdim(Dc / 128, Mc / 128);   // (2, 64)
    gemm_bias_kernel<<<gdim, 256>>>(obs, act, Dc, 2 * Dc, Wk,  bk,  pk,  Dc);
    gemm_bias_kernel<<<gdim, 256>>>(obs, act, Dc, 2 * Dc, Wv,  bv,  pv,  Dc);
    gemm_bias_kernel<<<gdim, 256>>>(obs, obs, Dc, Dc,     Wq,  bq,  pq,  Dc);
    gemm_bias_kernel<<<gdim, 256>>>(obs, obs, Dc, Dc,     Wks, bks, psk, Dc);
    gemm_bias_kernel<<<gdim, 256>>>(obs, obs, Dc, Dc,     Wvs, bvs, psv, Dc);

    dim3 adim(Lc / 512, Bc * Hc);    // (2, 64)
    attn_kernel<<<adim, 256>>>(pq, pk, pv, psk, psv, pmb, py);

    gemm_bias_kernel<<<gdim, 256>>>(py, py, Dc, Dc, Wp, bp, out, Dc);
}

// round 3
// speedup vs baseline: 1.0015x; 1.0015x over previous
#include <cuda_runtime.h>
#include <math.h>

#define Bc 8
#define Lc 1024
#define Dc 256
#define Hc 8
#define HDc 32
#define Mc (Bc*Lc)   // 8192

typedef unsigned long long ull;

// Scratch (allocation-free: __device__ globals)
__device__ float g_k[Mc*Dc];
__device__ float g_v[Mc*Dc];
__device__ float g_q[Mc*Dc];
__device__ float g_sk[Mc*Dc];
__device__ float g_sv[Mc*Dc];
__device__ float g_y[Mc*Dc];
__device__ unsigned g_mb[Bc*Lc*Lc/32];   // packed mask bits, 1MB

// ---- packed fp32 helpers (sm_103a f32x2 pipe) --------------------------------
__device__ __forceinline__ ull pk2(float x, float y) {
    ull r; asm("mov.b64 %0,{%1,%2};" : "=l"(r) : "f"(x), "f"(y)); return r;
}
__device__ __forceinline__ void upk2(ull v, float& x, float& y) {
    asm("mov.b64 {%0,%1},%2;" : "=f"(x), "=f"(y) : "l"(v));
}
__device__ __forceinline__ void ffma2(ull& d, ull a, ull b) {
    asm("fma.rn.f32x2 %0,%1,%2,%0;" : "+l"(d) : "l"(a), "l"(b));
}
__device__ __forceinline__ void fmul2(ull& d, ull a, ull b) {
    asm("mul.rn.f32x2 %0,%1,%2;" : "=l"(d) : "l"(a), "l"(b));
}
__device__ __forceinline__ float hadd2(ull a) {
    float x, y; upk2(a, x, y); return x + y;
}

// ---------------------------------------------------------------------------
// Mask pack: one bit per (b,l,j). Coalesced read, ballot, one word per warp.
// ---------------------------------------------------------------------------
__global__ __launch_bounds__(256)
void pack_mask_kernel(const int* __restrict__ mask, unsigned* __restrict__ mb)
{
    int i = blockIdx.x * 256 + threadIdx.x;
    unsigned bits = __ballot_sync(0xffffffffu, mask[i] != 0);
    if ((threadIdx.x & 31) == 0) mb[i >> 5] = bits;
}

// ---------------------------------------------------------------------------
// GEMM: C[M,N] = A[M,K] @ W[K,N] + bias. Tile 128x128x16, 256 thr, 8x8 micro.
// FFMA2 with W pre-duplicated in smem (zero pack instrs in mainloop).
// ---------------------------------------------------------------------------
__global__ __launch_bounds__(256)
void gemm_bias_kernel(const float* __restrict__ A0,
                      const float* __restrict__ A1,
                      int K0, int K,
                      const float* __restrict__ W,
                      const float* __restrict__ bias,
                      float* __restrict__ C, int N)
{
    __shared__ float As[16][132];     // [k][m], padded
    __shared__ ull   Ws2[16][128];    // [k][n], each entry = (w,w)

    const int tid = threadIdx.x;
    const int tx = tid & 15;
    const int ty = tid >> 4;
    const int m0 = blockIdx.y * 128;
    const int n0 = blockIdx.x * 128;
    const int K1 = K - K0;

    ull acc[4][8];
    #pragma unroll
    for (int i = 0; i < 4; i++)
        #pragma unroll
        for (int j = 0; j < 8; j++) acc[i][j] = 0ull;

    for (int k0 = 0; k0 < K; k0 += 16) {
        __syncthreads();
        // A tile 128x16, transposed store (m contiguous in smem)
        #pragma unroll
        for (int it = 0; it < 2; it++) {
            int idx = tid + it * 256;
            int m = idx >> 2, kq = (idx & 3) * 4;
            int gk = k0 + kq;
            float4 av;
            if (gk < K0) av = *(const float4*)&A0[(size_t)(m0 + m) * K0 + gk];
            else         av = *(const float4*)&A1[(size_t)(m0 + m) * K1 + gk - K0];
            As[kq + 0][m] = av.x; As[kq + 1][m] = av.y;
            As[kq + 2][m] = av.z; As[kq + 3][m] = av.w;
        }
        // W tile 16x128, duplicated entries
        #pragma unroll
        for (int it = 0; it < 2; it++) {
            int idx = tid + it * 256;
            int kk = idx >> 5, n = (idx & 31) * 4;
            float4 wv = *(const float4*)&W[(size_t)(k0 + kk) * N + n0 + n];
            Ws2[kk][n + 0] = pk2(wv.x, wv.x);
            Ws2[kk][n + 1] = pk2(wv.y, wv.y);
            Ws2[kk][n + 2] = pk2(wv.z, wv.z);
            Ws2[kk][n + 3] = pk2(wv.w, wv.w);
        }
        __syncthreads();
        #pragma unroll
        for (int kk = 0; kk < 16; kk++) {
            ulonglong2 a01 = *(const ulonglong2*)&As[kk][ty * 8];
            ulonglong2 a23 = *(const ulonglong2*)&As[kk][ty * 8 + 4];
            ull a2[4] = {a01.x, a01.y, a23.x, a23.y};
            ulonglong2 w01 = *(const ulonglong2*)&Ws2[kk][tx * 8 + 0];
            ulonglong2 w23 = *(const ulonglong2*)&Ws2[kk][tx * 8 + 2];
            ulonglong2 w45 = *(const ulonglong2*)&Ws2[kk][tx * 8 + 4];
            ulonglong2 w67 = *(const ulonglong2*)&Ws2[kk][tx * 8 + 6];
            ull w2[8] = {w01.x, w01.y, w23.x, w23.y, w45.x, w45.y, w67.x, w67.y};
            #pragma unroll
            for (int mp = 0; mp < 4; mp++)
                #pragma unroll
                for (int j = 0; j < 8; j++)
                    ffma2(acc[mp][j], a2[mp], w2[j]);
        }
    }

    // Epilogue
    float bcol[8];
    #pragma unroll
    for (int j = 0; j < 8; j++) bcol[j] = bias[n0 + tx * 8 + j];
    #pragma unroll
    for (int mp = 0; mp < 4; mp++) {
        float r0[8], r1[8];
        #pragma unroll
        for (int j = 0; j < 8; j++) {
            upk2(acc[mp][j], r0[j], r1[j]);
            r0[j] += bcol[j]; r1[j] += bcol[j];
        }
        int mA = m0 + ty * 8 + mp * 2;
        float* c0 = &C[(size_t)mA * N + n0 + tx * 8];
        float* c1 = c0 + N;
        *(float4*)&c0[0] = make_float4(r0[0], r0[1], r0[2], r0[3]);
        *(float4*)&c0[4] = make_float4(r0[4], r0[5], r0[6], r0[7]);
        *(float4*)&c1[0] = make_float4(r1[0], r1[1], r1[2], r1[3]);
        *(float4*)&c1[4] = make_float4(r1[4], r1[5], r1[6], r1[7]);
    }
}

// ---------------------------------------------------------------------------
// Attention: 256 threads, 2 query rows per thread (512 rows/block).
// Online softmax, FFMA2 throughout, K/V tiles read as ulonglong2.
// Diagonal term seeds the online state (value = self_v); j==l skipped.
// ---------------------------------------------------------------------------
__global__ __launch_bounds__(256)
void attn_kernel(const float* __restrict__ q,
                 const float* __restrict__ k,
                 const float* __restrict__ v,
                 const float* __restrict__ sk,
                 const float* __restrict__ sv,
                 const unsigned* __restrict__ mb,
                 float* __restrict__ y)
{
    __shared__ float Ks[128][HDc];
    __shared__ float Vs[128][HDc];

    const int bh = blockIdx.y;
    const int b = bh >> 3, h = bh & 7;
    const int l0 = blockIdx.x * 512;
    const int tid = threadIdx.x;
    const int la = l0 + tid;
    const int lb = la + 256;
    const int rowa = (b * Lc + la) * Dc + h * HDc;
    const int rowb = (b * Lc + lb) * Dc + h * HDc;
    const float scale = 0.17677669529663687f;   // 1/sqrt(32)
    const float NEG_INF = __int_as_float(0xff800000);
    const ull sc2 = pk2(scale, scale);

    // q (pre-scaled), as packed pairs
    ull qa[16], qb[16];
    #pragma unroll
    for (int i = 0; i < 8; i++) {
        ulonglong2 ta = *(const ulonglong2*)&q[rowa + i * 4];
        ulonglong2 tb = *(const ulonglong2*)&q[rowb + i * 4];
        fmul2(qa[2 * i], ta.x, sc2); fmul2(qa[2 * i + 1], ta.y, sc2);
        fmul2(qb[2 * i], tb.x, sc2); fmul2(qb[2 * i + 1], tb.y, sc2);
    }

    // diagonal scores
    ull da0 = 0, da1 = 0, db0 = 0, db1 = 0;
    #pragma unroll
    for (int i = 0; i < 8; i++) {
        ulonglong2 ka = *(const ulonglong2*)&sk[rowa + i * 4];
        ulonglong2 kb = *(const ulonglong2*)&sk[rowb + i * 4];
        ffma2(da0, qa[2 * i], ka.x); ffma2(da1, qa[2 * i + 1], ka.y);
        ffma2(db0, qb[2 * i], kb.x); ffma2(db1, qb[2 * i + 1], kb.y);
    }
    float swa = hadd2(da0) + hadd2(da1);
    float swb = hadd2(db0) + hadd2(db1);

    float ma = NEG_INF, suma = 0.f, mB = NEG_INF, sumb = 0.f;
    ull acca[16], accb[16];
    #pragma unroll
    for (int i = 0; i < 16; i++) { acca[i] = 0ull; accb[i] = 0ull; }

    {   // seed with diagonal term if mask diag set
        unsigned wa = mb[(unsigned)((b * Lc + la) * Lc + la) >> 5];
        unsigned wb = mb[(unsigned)((b * Lc + lb) * Lc + lb) >> 5];
        if ((wa >> (la & 31)) & 1u) {
            ma = swa; suma = 1.f;
            #pragma unroll
            for (int i = 0; i < 8; i++) {
                ulonglong2 t = *(const ulonglong2*)&sv[rowa + i * 4];
                acca[2 * i] = t.x; acca[2 * i + 1] = t.y;
            }
        }
        if ((wb >> (lb & 31)) & 1u) {
            mB = swb; sumb = 1.f;
            #pragma unroll
            for (int i = 0; i < 8; i++) {
                ulonglong2 t = *(const ulonglong2*)&sv[rowb + i * 4];
                accb[2 * i] = t.x; accb[2 * i + 1] = t.y;
            }
        }
    }

    const unsigned wbase_a = (unsigned)((b * Lc + la) * Lc) >> 5;
    const unsigned wbase_b = (unsigned)((b * Lc + lb) * Lc) >> 5;

    for (int j0 = 0; j0 < Lc; j0 += 128) {
        __syncthreads();
        #pragma unroll
        for (int it = 0; it < 4; it++) {
            int idx = tid + it * 256;
            int jj = idx >> 3, dd = (idx & 7) * 4;
            int g = (b * Lc + j0 + jj) * Dc + h * HDc + dd;
            *(float4*)&Ks[jj][dd] = *(const float4*)&k[g];
            *(float4*)&Vs[jj][dd] = *(const float4*)&v[g];
        }
        __syncthreads();

        unsigned mwa[4], mwb[4];
        #pragma unroll
        for (int w = 0; w < 4; w++) {
            mwa[w] = mb[wbase_a + (j0 >> 5) + w];
            mwb[w] = mb[wbase_b + (j0 >> 5) + w];
        }

        for (int jj = 0; jj < 128; jj++) {
            int j = j0 + jj;
            ull d0 = 0, d1 = 0, e0 = 0, e1 = 0;
            #pragma unroll
            for (int i = 0; i < 4; i++) {
                ulonglong2 k01 = *(const ulonglong2*)&Ks[jj][i * 8];
                ulonglong2 k23 = *(const ulonglong2*)&Ks[jj][i * 8 + 4];
                ffma2(d0, qa[i * 4 + 0], k01.x); ffma2(d1, qa[i * 4 + 1], k01.y);
                ffma2(d0, qa[i * 4 + 2], k23.x); ffma2(d1, qa[i * 4 + 3], k23.y);
                ffma2(e0, qb[i * 4 + 0], k01.x); ffma2(e1, qb[i * 4 + 1], k01.y);
                ffma2(e0, qb[i * 4 + 2], k23.x); ffma2(e1, qb[i * 4 + 3], k23.y);
            }
            float sa = hadd2(d0) + hadd2(d1);
            float sb = hadd2(e0) + hadd2(e1);

            bool ua = (((mwa[jj >> 5] >> (jj & 31)) & 1u) != 0u) && (j != la);
            bool ub = (((mwb[jj >> 5] >> (jj & 31)) & 1u) != 0u) && (j != lb);

            if (ua) {
                if (sa > ma) {
                    float corr = __expf(ma - sa);
                    ull c2 = pk2(corr, corr);
                    suma *= corr;
                    #pragma unroll
                    for (int i = 0; i < 16; i++) fmul2(acca[i], acca[i], c2);
                    ma = sa;
                }
                float p = __expf(sa - ma);
                suma += p;
                ull p2 = pk2(p, p);
                #pragma unroll
                for (int i = 0; i < 8; i++) {
                    ulonglong2 vv = *(const ulonglong2*)&Vs[jj][i * 4];
                    ffma2(acca[2 * i], p2, vv.x);
                    ffma2(acca[2 * i + 1], p2, vv.y);
                }
            }
            if (ub) {
                if (sb > mB) {
                    float corr = __expf(mB - sb);
                    ull c2 = pk2(corr, corr);
                    sumb *= corr;
                    #pragma unroll
                    for (int i = 0; i < 16; i++) fmul2(accb[i], accb[i], c2);
                    mB = sb;
                }
                float p = __expf(sb - mB);
                sumb += p;
                ull p2 = pk2(p, p);
                #pragma unroll
                for (int i = 0; i < 8; i++) {
                    ulonglong2 vv = *(const ulonglong2*)&Vs[jj][i * 4];
                    ffma2(accb[2 * i], p2, vv.x);
                    ffma2(accb[2 * i + 1], p2, vv.y);
                }
            }
        }
    }

    float inva = (suma > 0.f) ? (1.f / suma) : 0.f;
    float invb = (sumb > 0.f) ? (1.f / sumb) : 0.f;
    float oa[32], ob[32];
    #pragma unroll
    for (int p = 0; p < 16; p++) {
        upk2(acca[p], oa[2 * p], oa[2 * p + 1]);
        upk2(accb[p], ob[2 * p], ob[2 * p + 1]);
    }
    #pragma unroll
    for (int i = 0; i < 8; i++) {
        *(float4*)&y[rowa + i * 4] = make_float4(oa[4*i]*inva, oa[4*i+1]*inva,
                                                 oa[4*i+2]*inva, oa[4*i+3]*inva);
        *(float4*)&y[rowb + i * 4] = make_float4(ob[4*i]*invb, ob[4*i+1]*invb,
                                                 ob[4*i+2]*invb, ob[4*i+3]*invb);
    }
}

// ---------------------------------------------------------------------------
extern "C" void kernel_launch(void* const* d_in, const int* in_sizes, int n_in,
                              void* d_out, int out_size)
{
    const float* obs = (const float*)d_in[0];
    const float* act = (const float*)d_in[1];
    const int*   msk = (const int*)  d_in[2];
    const float* Wk  = (const float*)d_in[3];
    const float* bk  = (const float*)d_in[4];
    const float* Wv  = (const float*)d_in[5];
    const float* bv  = (const float*)d_in[6];
    const float* Wq  = (const float*)d_in[7];
    const float* bq  = (const float*)d_in[8];
    const float* Wks = (const float*)d_in[9];
    const float* bks = (const float*)d_in[10];
    const float* Wvs = (const float*)d_in[11];
    const float* bvs = (const float*)d_in[12];
    const float* Wp  = (const float*)d_in[13];
    const float* bp  = (const float*)d_in[14];
    float* out = (float*)d_out;

    float *pk, *pv, *pq, *psk, *psv, *py;
    unsigned* pmb;
    cudaGetSymbolAddress((void**)&pk,  g_k);
    cudaGetSymbolAddress((void**)&pv,  g_v);
    cudaGetSymbolAddress((void**)&pq,  g_q);
    cudaGetSymbolAddress((void**)&psk, g_sk);
    cudaGetSymbolAddress((void**)&psv, g_sv);
    cudaGetSymbolAddress((void**)&py,  g_y);
    cudaGetSymbolAddress((void**)&pmb, g_mb);

    // mask pack (1 bit per entry)
    pack_mask_kernel<<<(Bc*Lc*Lc)/256, 256>>>(msk, pmb);

    dim3 gdim(Dc / 128, Mc / 128);   // (2, 64)
    gemm_bias_kernel<<<gdim, 256>>>(obs, act, Dc, 2 * Dc, Wk,  bk,  pk,  Dc);
    gemm_bias_kernel<<<gdim, 256>>>(obs, act, Dc, 2 * Dc, Wv,  bv,  pv,  Dc);
    gemm_bias_kernel<<<gdim, 256>>>(obs, obs, Dc, Dc,     Wq,  bq,  pq,  Dc);
    gemm_bias_kernel<<<gdim, 256>>>(obs, obs, Dc, Dc,     Wks, bks, psk, Dc);
    gemm_bias_kernel<<<gdim, 256>>>(obs, obs, Dc, Dc,     Wvs, bvs, psv, Dc);

    dim3 adim(Lc / 512, Bc * Hc);    // (2, 64)
    attn_kernel<<<adim, 256>>>(pq, pk, pv, psk, psv, pmb, py);

    gemm_bias_kernel<<<gdim, 256>>>(py, py, Dc, Dc, Wp, bp, out, Dc);
}

// round 5
// speedup vs baseline: 1.9998x; 1.9967x over previous
#include <cuda_runtime.h>
#include <cuda_bf16.h>
#include <cstdint>
#include <math.h>

#define Bc 8
#define Lc 1024
#define Dc 256
#define Hc 8
#define HDc 32
#define Mc (Bc*Lc)   // 8192

typedef unsigned long long ull;

// ---------------- scratch (__device__ globals, allocation-free) -------------
__device__ float g_k[Mc*Dc];
__device__ float g_v[Mc*Dc];
__device__ float g_q[Mc*Dc];
__device__ float g_sk[Mc*Dc];
__device__ float g_sv[Mc*Dc];
__device__ float g_y[Mc*Dc];
__device__ unsigned g_mb[Bc*Lc*Lc/32];         // packed mask bits

__device__ __nv_bfloat16 g_aug_hi[Mc*2*Dc];    // [M][512] concat(obs,act) hi
__device__ __nv_bfloat16 g_aug_lo[Mc*2*Dc];
__device__ __nv_bfloat16 g_ys_hi[Mc*Dc];       // attn output split
__device__ __nv_bfloat16 g_ys_lo[Mc*Dc];
// transposed+split weights: [N=256][K] rows
#define OFF_WK  0
#define OFF_WV  131072
#define OFF_WQ  262144
#define OFF_WKS 327680
#define OFF_WVS 393216
#define OFF_WP  458752
__device__ __nv_bfloat16 g_wt_hi[524288];
__device__ __nv_bfloat16 g_wt_lo[524288];

// ---------------- packed fp32 helpers (attention) ----------------------------
__device__ __forceinline__ ull pk2(float x, float y) {
    ull r; asm("mov.b64 %0,{%1,%2};" : "=l"(r) : "f"(x), "f"(y)); return r;
}
__device__ __forceinline__ void upk2(ull v, float& x, float& y) {
    asm("mov.b64 {%0,%1},%2;" : "=f"(x), "=f"(y) : "l"(v));
}
__device__ __forceinline__ void ffma2(ull& d, ull a, ull b) {
    asm("fma.rn.f32x2 %0,%1,%2,%0;" : "+l"(d) : "l"(a), "l"(b));
}
__device__ __forceinline__ void fmul2(ull& d, ull a, ull b) {
    asm("mul.rn.f32x2 %0,%1,%2;" : "=l"(d) : "l"(a), "l"(b));
}
__device__ __forceinline__ float hadd2(ull a) {
    float x, y; upk2(a, x, y); return x + y;
}

__device__ __forceinline__ uint32_t s2u(const void* p) {
    uint32_t a;
    asm("{ .reg .u64 t; cvta.to.shared.u64 t, %1; cvt.u32.u64 %0, t; }"
        : "=r"(a) : "l"(p));
    return a;
}

// ---------------- HMMA helpers ------------------------------------------------
__device__ __forceinline__ void ldx4(uint32_t* r, uint32_t addr) {
    asm volatile("ldmatrix.sync.aligned.m8n8.x4.shared.b16 {%0,%1,%2,%3}, [%4];"
                 : "=r"(r[0]), "=r"(r[1]), "=r"(r[2]), "=r"(r[3]) : "r"(addr));
}
__device__ __forceinline__ void hmma(float* d, const uint32_t* a, const uint32_t* b) {
    asm volatile(
        "mma.sync.aligned.m16n8k16.row.col.f32.bf16.bf16.f32 "
        "{%0,%1,%2,%3}, {%4,%5,%6,%7}, {%8,%9}, {%0,%1,%2,%3};"
        : "+f"(d[0]), "+f"(d[1]), "+f"(d[2]), "+f"(d[3])
        : "r"(a[0]), "r"(a[1]), "r"(a[2]), "r"(a[3]), "r"(b[0]), "r"(b[1]));
}

// ---------------- small prep kernels -----------------------------------------
__global__ __launch_bounds__(256)
void pack_mask_kernel(const int* __restrict__ mask, unsigned* __restrict__ mb)
{
    int i = blockIdx.x * 256 + threadIdx.x;
    unsigned bits = __ballot_sync(0xffffffffu, mask[i] != 0);
    if ((threadIdx.x & 31) == 0) mb[i >> 5] = bits;
}

__global__ __launch_bounds__(256)
void aug_split_kernel(const float* __restrict__ obs, const float* __restrict__ act,
                      __nv_bfloat16* __restrict__ hi, __nv_bfloat16* __restrict__ lo)
{
    int idx = blockIdx.x * 256 + threadIdx.x;     // over M*512
    int m = idx >> 9, c = idx & 511;
    float x = (c < 256) ? obs[(m << 8) + c] : act[(m << 8) + (c - 256)];
    __nv_bfloat16 h = __float2bfloat16(x);
    hi[idx] = h;
    lo[idx] = __float2bfloat16(x - __bfloat162float(h));
}

__global__ __launch_bounds__(256)
void y_split_kernel(const float* __restrict__ y,
                    __nv_bfloat16* __restrict__ hi, __nv_bfloat16* __restrict__ lo)
{
    int idx = blockIdx.x * 256 + threadIdx.x;
    float x = y[idx];
    __nv_bfloat16 h = __float2bfloat16(x);
    hi[idx] = h;
    lo[idx] = __float2bfloat16(x - __bfloat162float(h));
}

// W [K][256] -> Wt hi/lo [256][K]
__global__ __launch_bounds__(256)
void w_split_kernel(const float* __restrict__ W, int K,
                    __nv_bfloat16* __restrict__ hi, __nv_bfloat16* __restrict__ lo)
{
    int idx = blockIdx.x * 256 + threadIdx.x;     // over K*256
    int k = idx >> 8, n = idx & 255;
    float x = W[idx];
    __nv_bfloat16 h = __float2bfloat16(x);
    hi[n * K + k] = h;
    lo[n * K + k] = __float2bfloat16(x - __bfloat162float(h));
}

// ---------------- HMMA GEMM ----------------------------------------------------
// C[M,256] = A[M,K] @ W[K,256] + bias via split-bf16 3-term emulation.
// A: hi/lo bf16 row-major pitch lda. Wt: hi/lo bf16 [256][K] row-major.
// Block tile 128x128, BK=64, 8 warps (2x4), warp tile 64x32.
#define GPITCH 72                     // smem row pitch (bf16 elems)
#define GOFF_AH 0
#define GOFF_AL (128*GPITCH)
#define GOFF_WH (2*128*GPITCH)
#define GOFF_WL (3*128*GPITCH)
#define GEMM_SMEM_BYTES (4*128*GPITCH*2)

__global__ __launch_bounds__(256)
void mma_gemm_kernel(const __nv_bfloat16* __restrict__ Ahi,
                     const __nv_bfloat16* __restrict__ Alo,
                     int lda, int K,
                     const __nv_bfloat16* __restrict__ Whi,
                     const __nv_bfloat16* __restrict__ Wlo,
                     const float* __restrict__ bias,
                     float* __restrict__ C)
{
    extern __shared__ __nv_bfloat16 sm[];
    const uint32_t sbase = s2u(sm);

    const int tid = threadIdx.x;
    const int lane = tid & 31, warp = tid >> 5;
    const int wm = warp >> 2;      // 0..1
    const int wn = warp & 3;       // 0..3
    const int m0 = blockIdx.y * 128;
    const int n0 = blockIdx.x * 128;

    // ldmatrix lane addressing
    const int a_row = wm * 64 + (lane & 15);
    const int a_col = ((lane >> 4) << 3);                 // 0 or 8
    const int bg = lane >> 3, bw = lane & 7;
    const int b_row = wn * 32 + ((bg >> 1) << 3) + bw;    // n within tile
    const int b_col = (bg & 1) << 3;

    uint32_t aAH[4], aAL[4], bAH[2], bAL[2];
    #pragma unroll
    for (int mf = 0; mf < 4; mf++) {
        uint32_t off = (uint32_t)((a_row + mf * 16) * GPITCH + a_col) * 2;
        aAH[mf] = sbase + GOFF_AH * 2 + off;
        aAL[mf] = sbase + GOFF_AL * 2 + off;
    }
    #pragma unroll
    for (int bt = 0; bt < 2; bt++) {
        uint32_t off = (uint32_t)((b_row + bt * 16) * GPITCH + b_col) * 2;
        bAH[bt] = sbase + GOFF_WH * 2 + off;
        bAL[bt] = sbase + GOFF_WL * 2 + off;
    }

    float d[4][4][4];
    #pragma unroll
    for (int i = 0; i < 4; i++)
        #pragma unroll
        for (int j = 0; j < 4; j++)
            #pragma unroll
            for (int t = 0; t < 4; t++) d[i][j][t] = 0.f;

    for (int k0 = 0; k0 < K; k0 += 64) {
        __syncthreads();
        #pragma unroll
        for (int t = 0; t < 4; t++) {
            int idx = tid + t * 256;          // 0..1023
            int r = idx >> 3;
            int e = (idx & 7) * 8;
            size_t ga = (size_t)(m0 + r) * lda + k0 + e;
            size_t gw = (size_t)(n0 + r) * K + k0 + e;
            *(uint4*)&sm[GOFF_AH + r * GPITCH + e] = *(const uint4*)&Ahi[ga];
            *(uint4*)&sm[GOFF_AL + r * GPITCH + e] = *(const uint4*)&Alo[ga];
            *(uint4*)&sm[GOFF_WH + r * GPITCH + e] = *(const uint4*)&Whi[gw];
            *(uint4*)&sm[GOFF_WL + r * GPITCH + e] = *(const uint4*)&Wlo[gw];
        }
        __syncthreads();

        #pragma unroll
        for (int ks = 0; ks < 4; ks++) {
            const uint32_t kb = ks * 32;      // 16 elems * 2B
            uint32_t ah[4][4], al[4][4];
            #pragma unroll
            for (int mf = 0; mf < 4; mf++) {
                ldx4(ah[mf], aAH[mf] + kb);
                ldx4(al[mf], aAL[mf] + kb);
            }
            uint32_t bh[4][2], bl[4][2];
            #pragma unroll
            for (int bt = 0; bt < 2; bt++) {
                uint32_t r4[4];
                ldx4(r4, bAH[bt] + kb);
                bh[2 * bt][0] = r4[0]; bh[2 * bt][1] = r4[1];
                bh[2 * bt + 1][0] = r4[2]; bh[2 * bt + 1][1] = r4[3];
                ldx4(r4, bAL[bt] + kb);
                bl[2 * bt][0] = r4[0]; bl[2 * bt][1] = r4[1];
                bl[2 * bt + 1][0] = r4[2]; bl[2 * bt + 1][1] = r4[3];
            }
            #pragma unroll
            for (int mf = 0; mf < 4; mf++)
                #pragma unroll
                for (int nf = 0; nf < 4; nf++) {
                    hmma(d[mf][nf], ah[mf], bh[nf]);
                    hmma(d[mf][nf], ah[mf], bl[nf]);
                    hmma(d[mf][nf], al[mf], bh[nf]);
                }
        }
    }

    // epilogue
    const int gm = m0 + wm * 64;
    const int gn = n0 + wn * 32;
    #pragma unroll
    for (int mf = 0; mf < 4; mf++)
        #pragma unroll
        for (int nf = 0; nf < 4; nf++) {
            int row = gm + mf * 16 + (lane >> 2);
            int col = gn + nf * 8 + (lane & 3) * 2;
            float b0 = bias[col], b1 = bias[col + 1];
            float2 o0 = make_float2(d[mf][nf][0] + b0, d[mf][nf][1] + b1);
            float2 o1 = make_float2(d[mf][nf][2] + b0, d[mf][nf][3] + b1);
            *(float2*)&C[(size_t)row * 256 + col] = o0;
            *(float2*)&C[(size_t)(row + 8) * 256 + col] = o1;
        }
}

// ---------------- attention (known-good from round 2) -------------------------
__global__ __launch_bounds__(256)
void attn_kernel(const float* __restrict__ q,
                 const float* __restrict__ k,
                 const float* __restrict__ v,
                 const float* __restrict__ sk,
                 const float* __restrict__ sv,
                 const unsigned* __restrict__ mb,
                 float* __restrict__ y)
{
    __shared__ float Ks[128][HDc];
    __shared__ float Vs[128][HDc];

    const int bh = blockIdx.y;
    const int b = bh >> 3, h = bh & 7;
    const int l0 = blockIdx.x * 512;
    const int tid = threadIdx.x;
    const int la = l0 + tid;
    const int lb = la + 256;
    const int rowa = (b * Lc + la) * Dc + h * HDc;
    const int rowb = (b * Lc + lb) * Dc + h * HDc;
    const float scale = 0.17677669529663687f;   // 1/sqrt(32)
    const float NEG_INF = __int_as_float(0xff800000);
    const ull sc2 = pk2(scale, scale);

    ull qa[16], qb[16];
    #pragma unroll
    for (int i = 0; i < 8; i++) {
        ulonglong2 ta = *(const ulonglong2*)&q[rowa + i * 4];
        ulonglong2 tb = *(const ulonglong2*)&q[rowb + i * 4];
        fmul2(qa[2 * i], ta.x, sc2); fmul2(qa[2 * i + 1], ta.y, sc2);
        fmul2(qb[2 * i], tb.x, sc2); fmul2(qb[2 * i + 1], tb.y, sc2);
    }

    ull da0 = 0, da1 = 0, db0 = 0, db1 = 0;
    #pragma unroll
    for (int i = 0; i < 8; i++) {
        ulonglong2 ka = *(const ulonglong2*)&sk[rowa + i * 4];
        ulonglong2 kb = *(const ulonglong2*)&sk[rowb + i * 4];
        ffma2(da0, qa[2 * i], ka.x); ffma2(da1, qa[2 * i + 1], ka.y);
        ffma2(db0, qb[2 * i], kb.x); ffma2(db1, qb[2 * i + 1], kb.y);
    }
    float swa = hadd2(da0) + hadd2(da1);
    float swb = hadd2(db0) + hadd2(db1);

    float ma = NEG_INF, suma = 0.f, mB = NEG_INF, sumb = 0.f;
    ull acca[16], accb[16];
    #pragma unroll
    for (int i = 0; i < 16; i++) { acca[i] = 0ull; accb[i] = 0ull; }

    {
        unsigned wa = mb[(unsigned)((b * Lc + la) * Lc + la) >> 5];
        unsigned wb = mb[(unsigned)((b * Lc + lb) * Lc + lb) >> 5];
        if ((wa >> (la & 31)) & 1u) {
            ma = swa; suma = 1.f;
            #pragma unroll
            for (int i = 0; i < 8; i++) {
                ulonglong2 t = *(const ulonglong2*)&sv[rowa + i * 4];
                acca[2 * i] = t.x; acca[2 * i + 1] = t.y;
            }
        }
        if ((wb >> (lb & 31)) & 1u) {
            mB = swb; sumb = 1.f;
            #pragma unroll
            for (int i = 0; i < 8; i++) {
                ulonglong2 t = *(const ulonglong2*)&sv[rowb + i * 4];
                accb[2 * i] = t.x; accb[2 * i + 1] = t.y;
            }
        }
    }

    const unsigned wbase_a = (unsigned)((b * Lc + la) * Lc) >> 5;
    const unsigned wbase_b = (unsigned)((b * Lc + lb) * Lc) >> 5;

    for (int j0 = 0; j0 < Lc; j0 += 128) {
        __syncthreads();
        #pragma unroll
        for (int it = 0; it < 4; it++) {
            int idx = tid + it * 256;
            int jj = idx >> 3, dd = (idx & 7) * 4;
            int g = (b * Lc + j0 + jj) * Dc + h * HDc + dd;
            *(float4*)&Ks[jj][dd] = *(const float4*)&k[g];
            *(float4*)&Vs[jj][dd] = *(const float4*)&v[g];
        }
        __syncthreads();

        unsigned mwa[4], mwb[4];
        #pragma unroll
        for (int w = 0; w < 4; w++) {
            mwa[w] = mb[wbase_a + (j0 >> 5) + w];
            mwb[w] = mb[wbase_b + (j0 >> 5) + w];
        }

        for (int jj = 0; jj < 128; jj++) {
            int j = j0 + jj;
            ull d0 = 0, d1 = 0, e0 = 0, e1 = 0;
            #pragma unroll
            for (int i = 0; i < 4; i++) {
                ulonglong2 k01 = *(const ulonglong2*)&Ks[jj][i * 8];
                ulonglong2 k23 = *(const ulonglong2*)&Ks[jj][i * 8 + 4];
                ffma2(d0, qa[i * 4 + 0], k01.x); ffma2(d1, qa[i * 4 + 1], k01.y);
                ffma2(d0, qa[i * 4 + 2], k23.x); ffma2(d1, qa[i * 4 + 3], k23.y);
                ffma2(e0, qb[i * 4 + 0], k01.x); ffma2(e1, qb[i * 4 + 1], k01.y);
                ffma2(e0, qb[i * 4 + 2], k23.x); ffma2(e1, qb[i * 4 + 3], k23.y);
            }
            float sa = hadd2(d0) + hadd2(d1);
            float sb = hadd2(e0) + hadd2(e1);

            bool ua = (((mwa[jj >> 5] >> (jj & 31)) & 1u) != 0u) && (j != la);
            bool ub = (((mwb[jj >> 5] >> (jj & 31)) & 1u) != 0u) && (j != lb);

            if (ua) {
                if (sa > ma) {
                    float corr = __expf(ma - sa);
                    ull c2 = pk2(corr, corr);
                    suma *= corr;
                    #pragma unroll
                    for (int i = 0; i < 16; i++) fmul2(acca[i], acca[i], c2);
                    ma = sa;
                }
                float p = __expf(sa - ma);
                suma += p;
                ull p2 = pk2(p, p);
                #pragma unroll
                for (int i = 0; i < 8; i++) {
                    ulonglong2 vv = *(const ulonglong2*)&Vs[jj][i * 4];
                    ffma2(acca[2 * i], p2, vv.x);
                    ffma2(acca[2 * i + 1], p2, vv.y);
                }
            }
            if (ub) {
                if (sb > mB) {
                    float corr = __expf(mB - sb);
                    ull c2 = pk2(corr, corr);
                    sumb *= corr;
                    #pragma unroll
                    for (int i = 0; i < 16; i++) fmul2(accb[i], accb[i], c2);
                    mB = sb;
                }
                float p = __expf(sb - mB);
                sumb += p;
                ull p2 = pk2(p, p);
                #pragma unroll
                for (int i = 0; i < 8; i++) {
                    ulonglong2 vv = *(const ulonglong2*)&Vs[jj][i * 4];
                    ffma2(accb[2 * i], p2, vv.x);
                    ffma2(accb[2 * i + 1], p2, vv.y);
                }
            }
        }
    }

    float inva = (suma > 0.f) ? (1.f / suma) : 0.f;
    float invb = (sumb > 0.f) ? (1.f / sumb) : 0.f;
    float oa[32], ob[32];
    #pragma unroll
    for (int p = 0; p < 16; p++) {
        upk2(acca[p], oa[2 * p], oa[2 * p + 1]);
        upk2(accb[p], ob[2 * p], ob[2 * p + 1]);
    }
    #pragma unroll
    for (int i = 0; i < 8; i++) {
        *(float4*)&y[rowa + i * 4] = make_float4(oa[4*i]*inva, oa[4*i+1]*inva,
                                                 oa[4*i+2]*inva, oa[4*i+3]*inva);
        *(float4*)&y[rowb + i * 4] = make_float4(ob[4*i]*invb, ob[4*i+1]*invb,
                                                 ob[4*i+2]*invb, ob[4*i+3]*invb);
    }
}

// ---------------------------------------------------------------------------
extern "C" void kernel_launch(void* const* d_in, const int* in_sizes, int n_in,
                              void* d_out, int out_size)
{
    const float* obs = (const float*)d_in[0];
    const float* act = (const float*)d_in[1];
    const int*   msk = (const int*)  d_in[2];
    const float* Wk  = (const float*)d_in[3];
    const float* bk  = (const float*)d_in[4];
    const float* Wv  = (const float*)d_in[5];
    const float* bv  = (const float*)d_in[6];
    const float* Wq  = (const float*)d_in[7];
    const float* bq  = (const float*)d_in[8];
    const float* Wks = (const float*)d_in[9];
    const float* bks = (const float*)d_in[10];
    const float* Wvs = (const float*)d_in[11];
    const float* bvs = (const float*)d_in[12];
    const float* Wp  = (const float*)d_in[13];
    const float* bp  = (const float*)d_in[14];
    float* out = (float*)d_out;

    float *pk, *pv, *pq, *psk, *psv, *py;
    unsigned* pmb;
    __nv_bfloat16 *paug_h, *paug_l, *pys_h, *pys_l, *pwt_h, *pwt_l;
    cudaGetSymbolAddress((void**)&pk,  g_k);
    cudaGetSymbolAddress((void**)&pv,  g_v);
    cudaGetSymbolAddress((void**)&pq,  g_q);
    cudaGetSymbolAddress((void**)&psk, g_sk);
    cudaGetSymbolAddress((void**)&psv, g_sv);
    cudaGetSymbolAddress((void**)&py,  g_y);
    cudaGetSymbolAddress((void**)&pmb, g_mb);
    cudaGetSymbolAddress((void**)&paug_h, g_aug_hi);
    cudaGetSymbolAddress((void**)&paug_l, g_aug_lo);
    cudaGetSymbolAddress((void**)&pys_h,  g_ys_hi);
    cudaGetSymbolAddress((void**)&pys_l,  g_ys_lo);
    cudaGetSymbolAddress((void**)&pwt_h,  g_wt_hi);
    cudaGetSymbolAddress((void**)&pwt_l,  g_wt_lo);

    cudaFuncSetAttribute(mma_gemm_kernel,
                         cudaFuncAttributeMaxDynamicSharedMemorySize, GEMM_SMEM_BYTES);

    // prep
    pack_mask_kernel<<<(Bc*Lc*Lc)/256, 256>>>(msk, pmb);
    aug_split_kernel<<<(Mc*2*Dc)/256, 256>>>(obs, act, paug_h, paug_l);
    w_split_kernel<<<(512*256)/256, 256>>>(Wk,  512, pwt_h + OFF_WK,  pwt_l + OFF_WK);
    w_split_kernel<<<(512*256)/256, 256>>>(Wv,  512, pwt_h + OFF_WV,  pwt_l + OFF_WV);
    w_split_kernel<<<(256*256)/256, 256>>>(Wq,  256, pwt_h + OFF_WQ,  pwt_l + OFF_WQ);
    w_split_kernel<<<(256*256)/256, 256>>>(Wks, 256, pwt_h + OFF_WKS, pwt_l + OFF_WKS);
    w_split_kernel<<<(256*256)/256, 256>>>(Wvs, 256, pwt_h + OFF_WVS, pwt_l + OFF_WVS);
    w_split_kernel<<<(256*256)/256, 256>>>(Wp,  256, pwt_h + OFF_WP,  pwt_l + OFF_WP);

    // projections (tensor core)
    dim3 gdim(2, Mc / 128);   // (n tiles, m tiles)
    mma_gemm_kernel<<<gdim, 256, GEMM_SMEM_BYTES>>>(paug_h, paug_l, 512, 512,
        pwt_h + OFF_WK,  pwt_l + OFF_WK,  bk,  pk);
    mma_gemm_kernel<<<gdim, 256, GEMM_SMEM_BYTES>>>(paug_h, paug_l, 512, 512,
        pwt_h + OFF_WV,  pwt_l + OFF_WV,  bv,  pv);
    mma_gemm_kernel<<<gdim, 256, GEMM_SMEM_BYTES>>>(paug_h, paug_l, 512, 256,
        pwt_h + OFF_WQ,  pwt_l + OFF_WQ,  bq,  pq);
    mma_gemm_kernel<<<gdim, 256, GEMM_SMEM_BYTES>>>(paug_h, paug_l, 512, 256,
        pwt_h + OFF_WKS, pwt_l + OFF_WKS, bks, psk);
    mma_gemm_kernel<<<gdim, 256, GEMM_SMEM_BYTES>>>(paug_h, paug_l, 512, 256,
        pwt_h + OFF_WVS, pwt_l + OFF_WVS, bvs, psv);

    // attention
    dim3 adim(Lc / 512, Bc * Hc);    // (2, 64)
    attn_kernel<<<adim, 256>>>(pq, pk, pv, psk, psv, pmb, py);

    // output projection
    y_split_kernel<<<(Mc*Dc)/256, 256>>>(py, pys_h, pys_l);
    mma_gemm_kernel<<<gdim, 256, GEMM_SMEM_BYTES>>>(pys_h, pys_l, 256, 256,
        pwt_h + OFF_WP,  pwt_l + OFF_WP,  bp, out);
}

// round 6
// speedup vs baseline: 2.0050x; 1.0026x over previous
#include <cuda_runtime.h>
#include <cuda_bf16.h>
#include <cstdint>
#include <math.h>

#define Bc 8
#define Lc 1024
#define Dc 256
#define Hc 8
#define HDc 32
#define Mc (Bc*Lc)   // 8192

typedef unsigned long long ull;

// ---------------- scratch (__device__ globals, allocation-free) -------------
__device__ float g_k[Mc*Dc];
__device__ float g_v[Mc*Dc];
__device__ float g_q[Mc*Dc];
__device__ float g_sk[Mc*Dc];
__device__ float g_sv[Mc*Dc];
__device__ float g_y[Mc*Dc];
__device__ unsigned g_mb[Bc*Lc*Lc/32];         // packed mask bits

__device__ __nv_bfloat16 g_aug_hi[Mc*2*Dc];    // [M][512] concat(obs,act) hi
__device__ __nv_bfloat16 g_aug_lo[Mc*2*Dc];
__device__ __nv_bfloat16 g_ys_hi[Mc*Dc];       // attn output split
__device__ __nv_bfloat16 g_ys_lo[Mc*Dc];
// transposed+split weights: [N=256][K] rows
#define OFF_WK  0
#define OFF_WV  131072
#define OFF_WQ  262144
#define OFF_WKS 327680
#define OFF_WVS 393216
#define OFF_WP  458752
__device__ __nv_bfloat16 g_wt_hi[524288];
__device__ __nv_bfloat16 g_wt_lo[524288];

// ---------------- packed fp32 helpers (attention) ----------------------------
__device__ __forceinline__ ull pk2(float x, float y) {
    ull r; asm("mov.b64 %0,{%1,%2};" : "=l"(r) : "f"(x), "f"(y)); return r;
}
__device__ __forceinline__ void upk2(ull v, float& x, float& y) {
    asm("mov.b64 {%0,%1},%2;" : "=f"(x), "=f"(y) : "l"(v));
}
__device__ __forceinline__ void ffma2(ull& d, ull a, ull b) {
    asm("fma.rn.f32x2 %0,%1,%2,%0;" : "+l"(d) : "l"(a), "l"(b));
}
__device__ __forceinline__ void fmul2(ull& d, ull a, ull b) {
    asm("mul.rn.f32x2 %0,%1,%2;" : "=l"(d) : "l"(a), "l"(b));
}
__device__ __forceinline__ float hadd2(ull a) {
    float x, y; upk2(a, x, y); return x + y;
}

__device__ __forceinline__ uint32_t s2u(const void* p) {
    uint32_t a;
    asm("{ .reg .u64 t; cvta.to.shared.u64 t, %1; cvt.u32.u64 %0, t; }"
        : "=r"(a) : "l"(p));
    return a;
}

// ---------------- HMMA helpers ------------------------------------------------
__device__ __forceinline__ void ldx4(uint32_t* r, uint32_t addr) {
    asm volatile("ldmatrix.sync.aligned.m8n8.x4.shared.b16 {%0,%1,%2,%3}, [%4];"
                 : "=r"(r[0]), "=r"(r[1]), "=r"(r[2]), "=r"(r[3]) : "r"(addr));
}
__device__ __forceinline__ void hmma(float* d, const uint32_t* a, const uint32_t* b) {
    asm volatile(
        "mma.sync.aligned.m16n8k16.row.col.f32.bf16.bf16.f32 "
        "{%0,%1,%2,%3}, {%4,%5,%6,%7}, {%8,%9}, {%0,%1,%2,%3};"
        : "+f"(d[0]), "+f"(d[1]), "+f"(d[2]), "+f"(d[3])
        : "r"(a[0]), "r"(a[1]), "r"(a[2]), "r"(a[3]), "r"(b[0]), "r"(b[1]));
}

// ---------------- small prep kernels -----------------------------------------
__global__ __launch_bounds__(256)
void pack_mask_kernel(const int* __restrict__ mask, unsigned* __restrict__ mb)
{
    int i = blockIdx.x * 256 + threadIdx.x;
    unsigned bits = __ballot_sync(0xffffffffu, mask[i] != 0);
    if ((threadIdx.x & 31) == 0) mb[i >> 5] = bits;
}

__global__ __launch_bounds__(256)
void aug_split_kernel(const float* __restrict__ obs, const float* __restrict__ act,
                      __nv_bfloat16* __restrict__ hi, __nv_bfloat16* __restrict__ lo)
{
    int idx = blockIdx.x * 256 + threadIdx.x;     // over M*512
    int m = idx >> 9, c = idx & 511;
    float x = (c < 256) ? obs[(m << 8) + c] : act[(m << 8) + (c - 256)];
    __nv_bfloat16 h = __float2bfloat16(x);
    hi[idx] = h;
    lo[idx] = __float2bfloat16(x - __bfloat162float(h));
}

__global__ __launch_bounds__(256)
void y_split_kernel(const float* __restrict__ y,
                    __nv_bfloat16* __restrict__ hi, __nv_bfloat16* __restrict__ lo)
{
    int idx = blockIdx.x * 256 + threadIdx.x;
    float x = y[idx];
    __nv_bfloat16 h = __float2bfloat16(x);
    hi[idx] = h;
    lo[idx] = __float2bfloat16(x - __bfloat162float(h));
}

// W [K][256] -> Wt hi/lo [256][K]
__global__ __launch_bounds__(256)
void w_split_kernel(const float* __restrict__ W, int K,
                    __nv_bfloat16* __restrict__ hi, __nv_bfloat16* __restrict__ lo)
{
    int idx = blockIdx.x * 256 + threadIdx.x;     // over K*256
    int k = idx >> 8, n = idx & 255;
    float x = W[idx];
    __nv_bfloat16 h = __float2bfloat16(x);
    hi[n * K + k] = h;
    lo[n * K + k] = __float2bfloat16(x - __bfloat162float(h));
}

// ---------------- HMMA GEMM ----------------------------------------------------
// C[M,256] = A[M,K] @ W[K,256] + bias via split-bf16 3-term emulation.
// A: hi/lo bf16 row-major pitch lda. Wt: hi/lo bf16 [256][K] row-major.
// Block tile 128x128, BK=64, 8 warps (2x4), warp tile 64x32.
#define GPITCH 72                     // smem row pitch (bf16 elems)
#define GOFF_AH 0
#define GOFF_AL (128*GPITCH)
#define GOFF_WH (2*128*GPITCH)
#define GOFF_WL (3*128*GPITCH)
#define GEMM_SMEM_BYTES (4*128*GPITCH*2)

__global__ __launch_bounds__(256)
void mma_gemm_kernel(const __nv_bfloat16* __restrict__ Ahi,
                     const __nv_bfloat16* __restrict__ Alo,
                     int lda, int K,
                     const __nv_bfloat16* __restrict__ Whi,
                     const __nv_bfloat16* __restrict__ Wlo,
                     const float* __restrict__ bias,
                     float* __restrict__ C)
{
    extern __shared__ __nv_bfloat16 sm[];
    const uint32_t sbase = s2u(sm);

    const int tid = threadIdx.x;
    const int lane = tid & 31, warp = tid >> 5;
    const int wm = warp >> 2;      // 0..1
    const int wn = warp & 3;       // 0..3
    const int m0 = blockIdx.y * 128;
    const int n0 = blockIdx.x * 128;

    // ldmatrix lane addressing
    const int a_row = wm * 64 + (lane & 15);
    const int a_col = ((lane >> 4) << 3);                 // 0 or 8
    const int bg = lane >> 3, bw = lane & 7;
    const int b_row = wn * 32 + ((bg >> 1) << 3) + bw;    // n within tile
    const int b_col = (bg & 1) << 3;

    uint32_t aAH[4], aAL[4], bAH[2], bAL[2];
    #pragma unroll
    for (int mf = 0; mf < 4; mf++) {
        uint32_t off = (uint32_t)((a_row + mf * 16) * GPITCH + a_col) * 2;
        aAH[mf] = sbase + GOFF_AH * 2 + off;
        aAL[mf] = sbase + GOFF_AL * 2 + off;
    }
    #pragma unroll
    for (int bt = 0; bt < 2; bt++) {
        uint32_t off = (uint32_t)((b_row + bt * 16) * GPITCH + b_col) * 2;
        bAH[bt] = sbase + GOFF_WH * 2 + off;
        bAL[bt] = sbase + GOFF_WL * 2 + off;
    }

    float d[4][4][4];
    #pragma unroll
    for (int i = 0; i < 4; i++)
        #pragma unroll
        for (int j = 0; j < 4; j++)
            #pragma unroll
            for (int t = 0; t < 4; t++) d[i][j][t] = 0.f;

    for (int k0 = 0; k0 < K; k0 += 64) {
        __syncthreads();
        #pragma unroll
        for (int t = 0; t < 4; t++) {
            int idx = tid + t * 256;          // 0..1023
            int r = idx >> 3;
            int e = (idx & 7) * 8;
            size_t ga = (size_t)(m0 + r) * lda + k0 + e;
            size_t gw = (size_t)(n0 + r) * K + k0 + e;
            *(uint4*)&sm[GOFF_AH + r * GPITCH + e] = *(const uint4*)&Ahi[ga];
            *(uint4*)&sm[GOFF_AL + r * GPITCH + e] = *(const uint4*)&Alo[ga];
            *(uint4*)&sm[GOFF_WH + r * GPITCH + e] = *(const uint4*)&Whi[gw];
            *(uint4*)&sm[GOFF_WL + r * GPITCH + e] = *(const uint4*)&Wlo[gw];
        }
        __syncthreads();

        #pragma unroll
        for (int ks = 0; ks < 4; ks++) {
            const uint32_t kb = ks * 32;      // 16 elems * 2B
            uint32_t ah[4][4], al[4][4];
            #pragma unroll
            for (int mf = 0; mf < 4; mf++) {
                ldx4(ah[mf], aAH[mf] + kb);
                ldx4(al[mf], aAL[mf] + kb);
            }
            uint32_t bh[4][2], bl[4][2];
            #pragma unroll
            for (int bt = 0; bt < 2; bt++) {
                uint32_t r4[4];
                ldx4(r4, bAH[bt] + kb);
                bh[2 * bt][0] = r4[0]; bh[2 * bt][1] = r4[1];
                bh[2 * bt + 1][0] = r4[2]; bh[2 * bt + 1][1] = r4[3];
                ldx4(r4, bAL[bt] + kb);
                bl[2 * bt][0] = r4[0]; bl[2 * bt][1] = r4[1];
                bl[2 * bt + 1][0] = r4[2]; bl[2 * bt + 1][1] = r4[3];
            }
            #pragma unroll
            for (int mf = 0; mf < 4; mf++)
                #pragma unroll
                for (int nf = 0; nf < 4; nf++) {
                    hmma(d[mf][nf], ah[mf], bh[nf]);
                    hmma(d[mf][nf], ah[mf], bl[nf]);
                    hmma(d[mf][nf], al[mf], bh[nf]);
                }
        }
    }

    // epilogue
    const int gm = m0 + wm * 64;
    const int gn = n0 + wn * 32;
    #pragma unroll
    for (int mf = 0; mf < 4; mf++)
        #pragma unroll
        for (int nf = 0; nf < 4; nf++) {
            int row = gm + mf * 16 + (lane >> 2);
            int col = gn + nf * 8 + (lane & 3) * 2;
            float b0 = bias[col], b1 = bias[col + 1];
            float2 o0 = make_float2(d[mf][nf][0] + b0, d[mf][nf][1] + b1);
            float2 o1 = make_float2(d[mf][nf][2] + b0, d[mf][nf][3] + b1);
            *(float2*)&C[(size_t)row * 256 + col] = o0;
            *(float2*)&C[(size_t)(row + 8) * 256 + col] = o1;
        }
}

// ---------------- attention (known-good from round 2) -------------------------
__global__ __launch_bounds__(256)
void attn_kernel(const float* __restrict__ q,
                 const float* __restrict__ k,
                 const float* __restrict__ v,
                 const float* __restrict__ sk,
                 const float* __restrict__ sv,
                 const unsigned* __restrict__ mb,
                 float* __restrict__ y)
{
    __shared__ float Ks[128][HDc];
    __shared__ float Vs[128][HDc];

    const int bh = blockIdx.y;
    const int b = bh >> 3, h = bh & 7;
    const int l0 = blockIdx.x * 512;
    const int tid = threadIdx.x;
    const int la = l0 + tid;
    const int lb = la + 256;
    const int rowa = (b * Lc + la) * Dc + h * HDc;
    const int rowb = (b * Lc + lb) * Dc + h * HDc;
    const float scale = 0.17677669529663687f;   // 1/sqrt(32)
    const float NEG_INF = __int_as_float(0xff800000);
    const ull sc2 = pk2(scale, scale);

    ull qa[16], qb[16];
    #pragma unroll
    for (int i = 0; i < 8; i++) {
        ulonglong2 ta = *(const ulonglong2*)&q[rowa + i * 4];
        ulonglong2 tb = *(const ulonglong2*)&q[rowb + i * 4];
        fmul2(qa[2 * i], ta.x, sc2); fmul2(qa[2 * i + 1], ta.y, sc2);
        fmul2(qb[2 * i], tb.x, sc2); fmul2(qb[2 * i + 1], tb.y, sc2);
    }

    ull da0 = 0, da1 = 0, db0 = 0, db1 = 0;
    #pragma unroll
    for (int i = 0; i < 8; i++) {
        ulonglong2 ka = *(const ulonglong2*)&sk[rowa + i * 4];
        ulonglong2 kb = *(const ulonglong2*)&sk[rowb + i * 4];
        ffma2(da0, qa[2 * i], ka.x); ffma2(da1, qa[2 * i + 1], ka.y);
        ffma2(db0, qb[2 * i], kb.x); ffma2(db1, qb[2 * i + 1], kb.y);
    }
    float swa = hadd2(da0) + hadd2(da1);
    float swb = hadd2(db0) + hadd2(db1);

    float ma = NEG_INF, suma = 0.f, mB = NEG_INF, sumb = 0.f;
    ull acca[16], accb[16];
    #pragma unroll
    for (int i = 0; i < 16; i++) { acca[i] = 0ull; accb[i] = 0ull; }

    {
        unsigned wa = mb[(unsigned)((b * Lc + la) * Lc + la) >> 5];
        unsigned wb = mb[(unsigned)((b * Lc + lb) * Lc + lb) >> 5];
        if ((wa >> (la & 31)) & 1u) {
            ma = swa; suma = 1.f;
            #pragma unroll
            for (int i = 0; i < 8; i++) {
                ulonglong2 t = *(const ulonglong2*)&sv[rowa + i * 4];
                acca[2 * i] = t.x; acca[2 * i + 1] = t.y;
            }
        }
        if ((wb >> (lb & 31)) & 1u) {
            mB = swb; sumb = 1.f;
            #pragma unroll
            for (int i = 0; i < 8; i++) {
                ulonglong2 t = *(const ulonglong2*)&sv[rowb + i * 4];
                accb[2 * i] = t.x; accb[2 * i + 1] = t.y;
            }
        }
    }

    const unsigned wbase_a = (unsigned)((b * Lc + la) * Lc) >> 5;
    const unsigned wbase_b = (unsigned)((b * Lc + lb) * Lc) >> 5;

    for (int j0 = 0; j0 < Lc; j0 += 128) {
        __syncthreads();
        #pragma unroll
        for (int it = 0; it < 4; it++) {
            int idx = tid + it * 256;
            int jj = idx >> 3, dd = (idx & 7) * 4;
            int g = (b * Lc + j0 + jj) * Dc + h * HDc + dd;
            *(float4*)&Ks[jj][dd] = *(const float4*)&k[g];
            *(float4*)&Vs[jj][dd] = *(const float4*)&v[g];
        }
        __syncthreads();

        unsigned mwa[4], mwb[4];
        #pragma unroll
        for (int w = 0; w < 4; w++) {
            mwa[w] = mb[wbase_a + (j0 >> 5) + w];
            mwb[w] = mb[wbase_b + (j0 >> 5) + w];
        }

        for (int jj = 0; jj < 128; jj++) {
            int j = j0 + jj;
            ull d0 = 0, d1 = 0, e0 = 0, e1 = 0;
            #pragma unroll
            for (int i = 0; i < 4; i++) {
                ulonglong2 k01 = *(const ulonglong2*)&Ks[jj][i * 8];
                ulonglong2 k23 = *(const ulonglong2*)&Ks[jj][i * 8 + 4];
                ffma2(d0, qa[i * 4 + 0], k01.x); ffma2(d1, qa[i * 4 + 1], k01.y);
                ffma2(d0, qa[i * 4 + 2], k23.x); ffma2(d1, qa[i * 4 + 3], k23.y);
                ffma2(e0, qb[i * 4 + 0], k01.x); ffma2(e1, qb[i * 4 + 1], k01.y);
                ffma2(e0, qb[i * 4 + 2], k23.x); ffma2(e1, qb[i * 4 + 3], k23.y);
            }
            float sa = hadd2(d0) + hadd2(d1);
            float sb = hadd2(e0) + hadd2(e1);

            bool ua = (((mwa[jj >> 5] >> (jj & 31)) & 1u) != 0u) && (j != la);
            bool ub = (((mwb[jj >> 5] >> (jj & 31)) & 1u) != 0u) && (j != lb);

            if (ua) {
                if (sa > ma) {
                    float corr = __expf(ma - sa);
                    ull c2 = pk2(corr, corr);
                    suma *= corr;
                    #pragma unroll
                    for (int i = 0; i < 16; i++) fmul2(acca[i], acca[i], c2);
                    ma = sa;
                }
                float p = __expf(sa - ma);
                suma += p;
                ull p2 = pk2(p, p);
                #pragma unroll
                for (int i = 0; i < 8; i++) {
                    ulonglong2 vv = *(const ulonglong2*)&Vs[jj][i * 4];
                    ffma2(acca[2 * i], p2, vv.x);
                    ffma2(acca[2 * i + 1], p2, vv.y);
                }
            }
            if (ub) {
                if (sb > mB) {
                    float corr = __expf(mB - sb);
                    ull c2 = pk2(corr, corr);
                    sumb *= corr;
                    #pragma unroll
                    for (int i = 0; i < 16; i++) fmul2(accb[i], accb[i], c2);
                    mB = sb;
                }
                float p = __expf(sb - mB);
                sumb += p;
                ull p2 = pk2(p, p);
                #pragma unroll
                for (int i = 0; i < 8; i++) {
                    ulonglong2 vv = *(const ulonglong2*)&Vs[jj][i * 4];
                    ffma2(accb[2 * i], p2, vv.x);
                    ffma2(accb[2 * i + 1], p2, vv.y);
                }
            }
        }
    }

    float inva = (suma > 0.f) ? (1.f / suma) : 0.f;
    float invb = (sumb > 0.f) ? (1.f / sumb) : 0.f;
    float oa[32], ob[32];
    #pragma unroll
    for (int p = 0; p < 16; p++) {
        upk2(acca[p], oa[2 * p], oa[2 * p + 1]);
        upk2(accb[p], ob[2 * p], ob[2 * p + 1]);
    }
    #pragma unroll
    for (int i = 0; i < 8; i++) {
        *(float4*)&y[rowa + i * 4] = make_float4(oa[4*i]*inva, oa[4*i+1]*inva,
                                                 oa[4*i+2]*inva, oa[4*i+3]*inva);
        *(float4*)&y[rowb + i * 4] = make_float4(ob[4*i]*invb, ob[4*i+1]*invb,
                                                 ob[4*i+2]*invb, ob[4*i+3]*invb);
    }
}

// ---------------------------------------------------------------------------
extern "C" void kernel_launch(void* const* d_in, const int* in_sizes, int n_in,
                              void* d_out, int out_size)
{
    const float* obs = (const float*)d_in[0];
    const float* act = (const float*)d_in[1];
    const int*   msk = (const int*)  d_in[2];
    const float* Wk  = (const float*)d_in[3];
    const float* bk  = (const float*)d_in[4];
    const float* Wv  = (const float*)d_in[5];
    const float* bv  = (const float*)d_in[6];
    const float* Wq  = (const float*)d_in[7];
    const float* bq  = (const float*)d_in[8];
    const float* Wks = (const float*)d_in[9];
    const float* bks = (const float*)d_in[10];
    const float* Wvs = (const float*)d_in[11];
    const float* bvs = (const float*)d_in[12];
    const float* Wp  = (const float*)d_in[13];
    const float* bp  = (const float*)d_in[14];
    float* out = (float*)d_out;

    float *pk, *pv, *pq, *psk, *psv, *py;
    unsigned* pmb;
    __nv_bfloat16 *paug_h, *paug_l, *pys_h, *pys_l, *pwt_h, *pwt_l;
    cudaGetSymbolAddress((void**)&pk,  g_k);
    cudaGetSymbolAddress((void**)&pv,  g_v);
    cudaGetSymbolAddress((void**)&pq,  g_q);
    cudaGetSymbolAddress((void**)&psk, g_sk);
    cudaGetSymbolAddress((void**)&psv, g_sv);
    cudaGetSymbolAddress((void**)&py,  g_y);
    cudaGetSymbolAddress((void**)&pmb, g_mb);
    cudaGetSymbolAddress((void**)&paug_h, g_aug_hi);
    cudaGetSymbolAddress((void**)&paug_l, g_aug_lo);
    cudaGetSymbolAddress((void**)&pys_h,  g_ys_hi);
    cudaGetSymbolAddress((void**)&pys_l,  g_ys_lo);
    cudaGetSymbolAddress((void**)&pwt_h,  g_wt_hi);
    cudaGetSymbolAddress((void**)&pwt_l,  g_wt_lo);

    cudaFuncSetAttribute(mma_gemm_kernel,
                         cudaFuncAttributeMaxDynamicSharedMemorySize, GEMM_SMEM_BYTES);

    // prep
    pack_mask_kernel<<<(Bc*Lc*Lc)/256, 256>>>(msk, pmb);
    aug_split_kernel<<<(Mc*2*Dc)/256, 256>>>(obs, act, paug_h, paug_l);
    w_split_kernel<<<(512*256)/256, 256>>>(Wk,  512, pwt_h + OFF_WK,  pwt_l + OFF_WK);
    w_split_kernel<<<(512*256)/256, 256>>>(Wv,  512, pwt_h + OFF_WV,  pwt_l + OFF_WV);
    w_split_kernel<<<(256*256)/256, 256>>>(Wq,  256, pwt_h + OFF_WQ,  pwt_l + OFF_WQ);
    w_split_kernel<<<(256*256)/256, 256>>>(Wks, 256, pwt_h + OFF_WKS, pwt_l + OFF_WKS);
    w_split_kernel<<<(256*256)/256, 256>>>(Wvs, 256, pwt_h + OFF_WVS, pwt_l + OFF_WVS);
    w_split_kernel<<<(256*256)/256, 256>>>(Wp,  256, pwt_h + OFF_WP,  pwt_l + OFF_WP);

    // projections (tensor core)
    dim3 gdim(2, Mc / 128);   // (n tiles, m tiles)
    mma_gemm_kernel<<<gdim, 256, GEMM_SMEM_BYTES>>>(paug_h, paug_l, 512, 512,
        pwt_h + OFF_WK,  pwt_l + OFF_WK,  bk,  pk);
    mma_gemm_kernel<<<gdim, 256, GEMM_SMEM_BYTES>>>(paug_h, paug_l, 512, 512,
        pwt_h + OFF_WV,  pwt_l + OFF_WV,  bv,  pv);
    mma_gemm_kernel<<<gdim, 256, GEMM_SMEM_BYTES>>>(paug_h, paug_l, 512, 256,
        pwt_h + OFF_WQ,  pwt_l + OFF_WQ,  bq,  pq);
    mma_gemm_kernel<<<gdim, 256, GEMM_SMEM_BYTES>>>(paug_h, paug_l, 512, 256,
        pwt_h + OFF_WKS, pwt_l + OFF_WKS, bks, psk);
    mma_gemm_kernel<<<gdim, 256, GEMM_SMEM_BYTES>>>(paug_h, paug_l, 512, 256,
        pwt_h + OFF_WVS, pwt_l + OFF_WVS, bvs, psv);

    // attention
    dim3 adim(Lc / 512, Bc * Hc);    // (2, 64)
    attn_kernel<<<adim, 256>>>(pq, pk, pv, psk, psv, pmb, py);

    // output projection
    y_split_kernel<<<(Mc*Dc)/256, 256>>>(py, pys_h, pys_l);
    mma_gemm_kernel<<<gdim, 256, GEMM_SMEM_BYTES>>>(pys_h, pys_l, 256, 256,
        pwt_h + OFF_WP,  pwt_l + OFF_WP,  bp, out);
}

// round 9
// speedup vs baseline: 3.3869x; 1.6893x over previous
#include <cuda_runtime.h>
#include <cuda_bf16.h>
#include <cstdint>
#include <math.h>

#define Bc 8
#define Lc 1024
#define Dc 256
#define Hc 8
#define HDc 32
#define Mc (Bc*Lc)

// ---------------- scratch ----------------------------------------------------
__device__ unsigned g_mb[Bc*Lc*Lc/32];
__device__ __align__(16) __nv_bfloat16 g_aug_hi[Mc*2*Dc];
__device__ __align__(16) __nv_bfloat16 g_aug_lo[Mc*2*Dc];
__device__ __align__(16) __nv_bfloat16 g_kh[Mc*Dc],  g_kl[Mc*Dc];
__device__ __align__(16) __nv_bfloat16 g_vh[Mc*Dc],  g_vl[Mc*Dc];
__device__ __align__(16) __nv_bfloat16 g_qh[Mc*Dc],  g_ql[Mc*Dc];
__device__ __align__(16) __nv_bfloat16 g_skh[Mc*Dc], g_skl[Mc*Dc];
__device__ __align__(16) __nv_bfloat16 g_svh[Mc*Dc], g_svl[Mc*Dc];
__device__ __align__(16) __nv_bfloat16 g_yh[Mc*Dc],  g_yl[Mc*Dc];
#define OFF_WK  0
#define OFF_WV  131072
#define OFF_WQ  262144
#define OFF_WKS 327680
#define OFF_WVS 393216
#define OFF_WP  458752
__device__ __align__(16) __nv_bfloat16 g_wt_hi[524288];
__device__ __align__(16) __nv_bfloat16 g_wt_lo[524288];

// ---------------- helpers -----------------------------------------------------
__device__ __forceinline__ uint32_t s2u(const void* p) {
    uint32_t a;
    asm("{ .reg .u64 t; cvta.to.shared.u64 t, %1; cvt.u32.u64 %0, t; }" : "=r"(a) : "l"(p));
    return a;
}
__device__ __forceinline__ void ldx4(uint32_t* r, uint32_t addr) {
    asm volatile("ldmatrix.sync.aligned.m8n8.x4.shared.b16 {%0,%1,%2,%3}, [%4];"
                 : "=r"(r[0]), "=r"(r[1]), "=r"(r[2]), "=r"(r[3]) : "r"(addr));
}
__device__ __forceinline__ void ldx4t(uint32_t* r, uint32_t addr) {
    asm volatile("ldmatrix.sync.aligned.m8n8.x4.trans.shared.b16 {%0,%1,%2,%3}, [%4];"
                 : "=r"(r[0]), "=r"(r[1]), "=r"(r[2]), "=r"(r[3]) : "r"(addr));
}
__device__ __forceinline__ void hmma(float* d, const uint32_t* a, const uint32_t* b) {
    asm volatile(
        "mma.sync.aligned.m16n8k16.row.col.f32.bf16.bf16.f32 "
        "{%0,%1,%2,%3}, {%4,%5,%6,%7}, {%8,%9}, {%0,%1,%2,%3};"
        : "+f"(d[0]), "+f"(d[1]), "+f"(d[2]), "+f"(d[3])
        : "r"(a[0]), "r"(a[1]), "r"(a[2]), "r"(a[3]), "r"(b[0]), "r"(b[1]));
}
__device__ __forceinline__ uint32_t cvt2(float hi, float lo) {  // pack {hi,lo}
    uint32_t d; asm("cvt.rn.bf16x2.f32 %0,%1,%2;" : "=r"(d) : "f"(hi), "f"(lo)); return d;
}
__device__ __forceinline__ float exp2p(float x) {    // FMA-pipe 2^x, x<=0
    x = fmaxf(x, -126.f);
    float t = x + 12582912.f;
    int n = __float_as_int(t) - 0x4B400000;
    float f = x - (t - 12582912.f);
    float p = 0.0013333558f;
    p = fmaf(p, f, 0.0096181291f);
    p = fmaf(p, f, 0.0555041087f);
    p = fmaf(p, f, 0.2402265069f);
    p = fmaf(p, f, 0.6931471806f);
    p = fmaf(p, f, 1.0f);
    return __int_as_float((n + 127) << 23) * p;
}

// ---------------- prep ---------------------------------------------------------
__global__ __launch_bounds__(256)
void pack_mask_kernel(const int* __restrict__ mask, unsigned* __restrict__ mb)
{
    int i = blockIdx.x * 256 + threadIdx.x;
    unsigned bits = __ballot_sync(0xffffffffu, mask[i] != 0);
    if ((threadIdx.x & 31) == 0) mb[i >> 5] = bits;
}

__global__ __launch_bounds__(256)
void aug_split_kernel(const float* __restrict__ obs, const float* __restrict__ act,
                      __nv_bfloat16* __restrict__ hi, __nv_bfloat16* __restrict__ lo)
{
    int idx = blockIdx.x * 256 + threadIdx.x;
    int m = idx >> 9, c = idx & 511;
    float x = (c < 256) ? obs[(m << 8) + c] : act[(m << 8) + (c - 256)];
    __nv_bfloat16 h = __float2bfloat16(x);
    hi[idx] = h;
    lo[idx] = __float2bfloat16(x - __bfloat162float(h));
}

// W [K][256] -> Wt hi/lo [256][K] (tiled transpose)
__global__ __launch_bounds__(256)
void w_split_t_kernel(const float* __restrict__ W, int K,
                      __nv_bfloat16* __restrict__ hi, __nv_bfloat16* __restrict__ lo)
{
    __shared__ float tile[32][33];
    int x = threadIdx.x & 31, y = threadIdx.x >> 5;
    int nt = blockIdx.x * 32, kt = blockIdx.y * 32;
    #pragma unroll
    for (int i = 0; i < 4; i++)
        tile[y + i * 8][x] = W[(size_t)(kt + y + i * 8) * 256 + nt + x];
    __syncthreads();
    #pragma unroll
    for (int i = 0; i < 4; i++) {
        int n = nt + y + i * 8, k = kt + x;
        float v = tile[x][y + i * 8];
        __nv_bfloat16 h = __float2bfloat16(v);
        hi[(size_t)n * K + k] = h;
        lo[(size_t)n * K + k] = __float2bfloat16(v - __bfloat162float(h));
    }
}

// ---------------- HMMA GEMM -----------------------------------------------------
#define GPITCH 72
#define GOFF_AH 0
#define GOFF_AL (128*GPITCH)
#define GOFF_WH (2*128*GPITCH)
#define GOFF_WL (3*128*GPITCH)
#define GEMM_SMEM_BYTES (4*128*GPITCH*2)

__global__ __launch_bounds__(256)
void mma_gemm_kernel(const __nv_bfloat16* __restrict__ Ahi,
                     const __nv_bfloat16* __restrict__ Alo,
                     int lda, int K,
                     const __nv_bfloat16* __restrict__ Whi,
                     const __nv_bfloat16* __restrict__ Wlo,
                     const float* __restrict__ bias, float alpha,
                     float* __restrict__ Cf,
                     __nv_bfloat16* __restrict__ Chi,
                     __nv_bfloat16* __restrict__ Clo)
{
    extern __shared__ __nv_bfloat16 smg[];
    const uint32_t sbase = s2u(smg);
    const int tid = threadIdx.x;
    const int lane = tid & 31, warp = tid >> 5;
    const int wm = warp >> 2, wn = warp & 3;
    const int m0 = blockIdx.y * 128, n0 = blockIdx.x * 128;

    const int a_row = wm * 64 + (lane & 15);
    const int a_col = ((lane >> 4) << 3);
    const int bg = lane >> 3, bw = lane & 7;
    const int b_row = wn * 32 + ((bg >> 1) << 3) + bw;
    const int b_col = (bg & 1) << 3;

    uint32_t aAH[4], aAL[4], bAH[2], bAL[2];
    #pragma unroll
    for (int mf = 0; mf < 4; mf++) {
        uint32_t off = (uint32_t)((a_row + mf * 16) * GPITCH + a_col) * 2;
        aAH[mf] = sbase + GOFF_AH * 2 + off;
        aAL[mf] = sbase + GOFF_AL * 2 + off;
    }
    #pragma unroll
    for (int bt = 0; bt < 2; bt++) {
        uint32_t off = (uint32_t)((b_row + bt * 16) * GPITCH + b_col) * 2;
        bAH[bt] = sbase + GOFF_WH * 2 + off;
        bAL[bt] = sbase + GOFF_WL * 2 + off;
    }

    float d[4][4][4];
    #pragma unroll
    for (int i = 0; i < 4; i++)
        #pragma unroll
        for (int j = 0; j < 4; j++)
            #pragma unroll
            for (int t = 0; t < 4; t++) d[i][j][t] = 0.f;

    for (int k0 = 0; k0 < K; k0 += 64) {
        __syncthreads();
        #pragma unroll
        for (int t = 0; t < 4; t++) {
            int idx = tid + t * 256;
            int r = idx >> 3, e = (idx & 7) * 8;
            size_t ga = (size_t)(m0 + r) * lda + k0 + e;
            size_t gw = (size_t)(n0 + r) * K + k0 + e;
            *(uint4*)&smg[GOFF_AH + r * GPITCH + e] = *(const uint4*)&Ahi[ga];
            *(uint4*)&smg[GOFF_AL + r * GPITCH + e] = *(const uint4*)&Alo[ga];
            *(uint4*)&smg[GOFF_WH + r * GPITCH + e] = *(const uint4*)&Whi[gw];
            *(uint4*)&smg[GOFF_WL + r * GPITCH + e] = *(const uint4*)&Wlo[gw];
        }
        __syncthreads();
        #pragma unroll
        for (int ks = 0; ks < 4; ks++) {
            const uint32_t kb = ks * 32;
            uint32_t ah[4][4], al[4][4];
            #pragma unroll
            for (int mf = 0; mf < 4; mf++) { ldx4(ah[mf], aAH[mf] + kb); ldx4(al[mf], aAL[mf] + kb); }
            uint32_t bh[4][2], bl[4][2];
            #pragma unroll
            for (int bt = 0; bt < 2; bt++) {
                uint32_t r4[4];
                ldx4(r4, bAH[bt] + kb);
                bh[2*bt][0]=r4[0]; bh[2*bt][1]=r4[1]; bh[2*bt+1][0]=r4[2]; bh[2*bt+1][1]=r4[3];
                ldx4(r4, bAL[bt] + kb);
                bl[2*bt][0]=r4[0]; bl[2*bt][1]=r4[1]; bl[2*bt+1][0]=r4[2]; bl[2*bt+1][1]=r4[3];
            }
            #pragma unroll
            for (int mf = 0; mf < 4; mf++)
                #pragma unroll
                for (int nf = 0; nf < 4; nf++) {
                    hmma(d[mf][nf], ah[mf], bh[nf]);
                    hmma(d[mf][nf], ah[mf], bl[nf]);
                    hmma(d[mf][nf], al[mf], bh[nf]);
                }
        }
    }

    const int gm = m0 + wm * 64, gn = n0 + wn * 32;
    #pragma unroll
    for (int mf = 0; mf < 4; mf++)
        #pragma unroll
        for (int nf = 0; nf < 4; nf++) {
            int row = gm + mf * 16 + (lane >> 2);
            int col = gn + nf * 8 + (lane & 3) * 2;
            float b0 = bias[col], b1 = bias[col + 1];
            float v0 = alpha * (d[mf][nf][0] + b0);
            float v1 = alpha * (d[mf][nf][1] + b1);
            float v2 = alpha * (d[mf][nf][2] + b0);
            float v3 = alpha * (d[mf][nf][3] + b1);
            if (Cf) {
                *(float2*)&Cf[(size_t)row * 256 + col] = make_float2(v0, v1);
                *(float2*)&Cf[(size_t)(row + 8) * 256 + col] = make_float2(v2, v3);
            } else {
                uint32_t h01 = cvt2(v1, v0), h23 = cvt2(v3, v2);
                float l0 = v0 - __int_as_float(h01 << 16);
                float l1 = v1 - __int_as_float(h01 & 0xffff0000u);
                float l2 = v2 - __int_as_float(h23 << 16);
                float l3 = v3 - __int_as_float(h23 & 0xffff0000u);
                *(uint32_t*)&Chi[(size_t)row * 256 + col] = h01;
                *(uint32_t*)&Clo[(size_t)row * 256 + col] = cvt2(l1, l0);
                *(uint32_t*)&Chi[(size_t)(row + 8) * 256 + col] = h23;
                *(uint32_t*)&Clo[(size_t)(row + 8) * 256 + col] = cvt2(l3, l2);
            }
        }
}

// ---------------- HMMA flash attention ------------------------------------------
// q pre-scaled by log2(e)/sqrt(hd); softmax in base-2. 8 warps x 16 q rows.
#define AP 40
#define ATTN_SMEM_BYTES (6*128*AP*2)

__global__ __launch_bounds__(256)
void attn_mma_kernel(const __nv_bfloat16* __restrict__ qh_, const __nv_bfloat16* __restrict__ ql_,
                     const __nv_bfloat16* __restrict__ kh_, const __nv_bfloat16* __restrict__ kl_,
                     const __nv_bfloat16* __restrict__ vh_, const __nv_bfloat16* __restrict__ vl_,
                     const __nv_bfloat16* __restrict__ skh_, const __nv_bfloat16* __restrict__ skl_,
                     const __nv_bfloat16* __restrict__ svh_, const __nv_bfloat16* __restrict__ svl_,
                     const unsigned* __restrict__ mb,
                     __nv_bfloat16* __restrict__ yh_, __nv_bfloat16* __restrict__ yl_)
{
    extern __shared__ __nv_bfloat16 shm[];
    // elem offsets: QH 0, QL 5120, KH 10240, KL 15360, VH 20480, VL 25600
    const int tid = threadIdx.x, lane = tid & 31, wq = tid >> 5;
    const int b = blockIdx.y >> 3, h = blockIdx.y & 7;
    const int l0 = blockIdx.x << 7;
    const uint32_t sb = s2u(shm);

    // ---- Q tile: 128 rows x 32 cols = 512 uint4 -> 2 per thread ----
    #pragma unroll
    for (int t = 0; t < 2; t++) {
        int idx = tid + t * 256;
        int rr = idx >> 2, c8 = (idx & 3) * 8;
        size_t g = ((size_t)(b * Lc + l0 + rr)) * Dc + h * HDc + c8;
        *(uint4*)&shm[0    + rr * AP + c8] = *(const uint4*)&qh_[g];
        *(uint4*)&shm[5120 + rr * AP + c8] = *(const uint4*)&ql_[g];
    }
    __syncthreads();

    uint32_t aH[2][4], aL[2][4];
    {
        uint32_t ab = sb + (uint32_t)(wq * 16 + (lane & 15)) * (AP * 2) + ((lane >> 4) << 4);
        ldx4(aH[0], ab);         ldx4(aH[1], ab + 32);
        ldx4(aL[0], ab + 10240); ldx4(aL[1], ab + 10240 + 32);
    }

    const int rl0 = wq * 16 + (lane >> 2);
    const int rowg0 = l0 + rl0, rowg1 = rowg0 + 8;

    float sw[2];
    #pragma unroll
    for (int r2 = 0; r2 < 2; r2++) {
        int rl = rl0 + r2 * 8;
        size_t g = ((size_t)(b * Lc + l0 + rl)) * Dc + h * HDc + (lane & 3) * 8;
        float s = 0.f;
        #pragma unroll
        for (int dd = 0; dd < 8; dd++) {
            float qv = __bfloat162float(shm[rl * AP + (lane & 3) * 8 + dd])
                     + __bfloat162float(shm[5120 + rl * AP + (lane & 3) * 8 + dd]);
            float kv = __bfloat162float(skh_[g + dd]) + __bfloat162float(skl_[g + dd]);
            s += qv * kv;
        }
        s += __shfl_xor_sync(0xffffffffu, s, 1);
        s += __shfl_xor_sync(0xffffffffu, s, 2);
        sw[r2] = s;
    }

    float m0 = -1e30f, m1 = -1e30f, sum0 = 0.f, sum1 = 0.f;
    float acc[4][4];
    #pragma unroll
    for (int i = 0; i < 4; i++) { acc[i][0]=0.f; acc[i][1]=0.f; acc[i][2]=0.f; acc[i][3]=0.f; }

    for (int j0 = 0; j0 < Lc; j0 += 128) {
        __syncthreads();
        // ---- K/V tiles: 4 arrays x 512 uint4 -> 8 uint4 per thread ----
        #pragma unroll
        for (int t = 0; t < 2; t++) {
            int idx = tid + t * 256;
            int rr = idx >> 2, c8 = (idx & 3) * 8;
            size_t g = ((size_t)b * Lc + j0 + rr) * Dc + h * HDc + c8;
            *(uint4*)&shm[10240 + rr * AP + c8] = *(const uint4*)&kh_[g];
            *(uint4*)&shm[15360 + rr * AP + c8] = *(const uint4*)&kl_[g];
            *(uint4*)&shm[20480 + rr * AP + c8] = *(const uint4*)&vh_[g];
            *(uint4*)&shm[25600 + rr * AP + c8] = *(const uint4*)&vl_[g];
        }
        __syncthreads();

        float S[16][4];
        #pragma unroll
        for (int i = 0; i < 16; i++) { S[i][0]=0.f; S[i][1]=0.f; S[i][2]=0.f; S[i][3]=0.f; }

        #pragma unroll
        for (int kc = 0; kc < 2; kc++) {
            #pragma unroll
            for (int bt = 0; bt < 8; bt++) {
                uint32_t ka = sb + 20480
                            + (uint32_t)(bt * 16 + ((lane >> 4) << 3) + (lane & 7)) * (AP * 2)
                            + (((lane >> 3) & 1) << 4) + kc * 32;
                uint32_t rh[4], rl4[4];
                ldx4(rh, ka);
                ldx4(rl4, ka + 10240);
                hmma(S[2*bt],   aH[kc], rh);     hmma(S[2*bt],   aH[kc], rl4);
                hmma(S[2*bt],   aL[kc], rh);
                hmma(S[2*bt+1], aH[kc], rh+2);   hmma(S[2*bt+1], aH[kc], rl4+2);
                hmma(S[2*bt+1], aL[kc], rh+2);
            }
        }

        unsigned mw0[4], mw1[4];
        #pragma unroll
        for (int w = 0; w < 4; w++) {
            mw0[w] = mb[((size_t)b * Lc + rowg0) * 32 + (j0 >> 5) + w];
            mw1[w] = mb[((size_t)b * Lc + rowg1) * 32 + (j0 >> 5) + w];
        }
        float mn0 = m0, mn1 = m1;
        #pragma unroll
        for (int nf = 0; nf < 16; nf++) {
            unsigned w0 = mw0[nf >> 2], w1 = mw1[nf >> 2];
            int sh = ((nf & 3) << 3) + ((lane & 3) << 1);
            int colg = j0 + nf * 8 + ((lane & 3) << 1);
            #pragma unroll
            for (int e = 0; e < 2; e++) {
                bool ok0 = (((w0 >> (sh + e)) & 1u) != 0u) && (colg + e != rowg0);
                bool ok1 = (((w1 >> (sh + e)) & 1u) != 0u) && (colg + e != rowg1);
                float s0 = ok0 ? S[nf][e]     : -1e30f;
                float s1 = ok1 ? S[nf][e + 2] : -1e30f;
                S[nf][e] = s0; S[nf][e + 2] = s1;
                mn0 = fmaxf(mn0, s0); mn1 = fmaxf(mn1, s1);
            }
        }
        mn0 = fmaxf(mn0, __shfl_xor_sync(0xffffffffu, mn0, 1));
        mn0 = fmaxf(mn0, __shfl_xor_sync(0xffffffffu, mn0, 2));
        mn1 = fmaxf(mn1, __shfl_xor_sync(0xffffffffu, mn1, 1));
        mn1 = fmaxf(mn1, __shfl_xor_sync(0xffffffffu, mn1, 2));

        float c0 = exp2p(m0 - mn0), c1 = exp2p(m1 - mn1);
        m0 = mn0; m1 = mn1;
        #pragma unroll
        for (int nf = 0; nf < 4; nf++) {
            acc[nf][0] *= c0; acc[nf][1] *= c0; acc[nf][2] *= c1; acc[nf][3] *= c1;
        }

        float ps0 = 0.f, ps1 = 0.f;
        #pragma unroll
        for (int nf = 0; nf < 16; nf++) {
            float p0 = exp2p(S[nf][0] - m0), p1 = exp2p(S[nf][1] - m0);
            float p2 = exp2p(S[nf][2] - m1), p3 = exp2p(S[nf][3] - m1);
            S[nf][0] = p0; S[nf][1] = p1; S[nf][2] = p2; S[nf][3] = p3;
            ps0 += p0 + p1; ps1 += p2 + p3;
        }
        ps0 += __shfl_xor_sync(0xffffffffu, ps0, 1);
        ps0 += __shfl_xor_sync(0xffffffffu, ps0, 2);
        ps1 += __shfl_xor_sync(0xffffffffu, ps1, 1);
        ps1 += __shfl_xor_sync(0xffffffffu, ps1, 2);
        sum0 = sum0 * c0 + ps0;
        sum1 = sum1 * c1 + ps1;

        #pragma unroll
        for (int kc = 0; kc < 8; kc++) {
            uint32_t aph[4], apl[4];
            #pragma unroll
            for (int half = 0; half < 2; half++) {
                int nf = 2 * kc + half;
                uint32_t hA = cvt2(S[nf][1], S[nf][0]);
                uint32_t hB = cvt2(S[nf][3], S[nf][2]);
                float l0f = S[nf][0] - __int_as_float(hA << 16);
                float l1f = S[nf][1] - __int_as_float(hA & 0xffff0000u);
                float l2f = S[nf][2] - __int_as_float(hB << 16);
                float l3f = S[nf][3] - __int_as_float(hB & 0xffff0000u);
                aph[2 * half]     = hA;
                aph[2 * half + 1] = hB;
                apl[2 * half]     = cvt2(l1f, l0f);
                apl[2 * half + 1] = cvt2(l3f, l2f);
            }
            uint32_t vbase = sb + 40960
                           + (uint32_t)(kc * 16 + ((lane >> 3) & 1) * 8 + (lane & 7)) * (AP * 2)
                           + ((lane >> 4) << 4);
            #pragma unroll
            for (int part = 0; part < 2; part++) {
                uint32_t vh4[4], vl4[4];
                uint32_t va = vbase + part * 32;
                ldx4t(vh4, va);
                ldx4t(vl4, va + 10240);
                int nf = part * 2;
                hmma(acc[nf],   aph, vh4);     hmma(acc[nf],   aph, vl4);
                hmma(acc[nf],   apl, vh4);
                hmma(acc[nf+1], aph, vh4+2);   hmma(acc[nf+1], aph, vl4+2);
                hmma(acc[nf+1], apl, vh4+2);
            }
        }
    }

    #pragma unroll
    for (int r2 = 0; r2 < 2; r2++) {
        int rowg = r2 ? rowg1 : rowg0;
        float mm = r2 ? m1 : m0, ss = r2 ? sum1 : sum0;
        unsigned dbit = (mb[((size_t)b * Lc + rowg) * 32 + (rowg >> 5)] >> (rowg & 31)) & 1u;
        float mf = dbit ? fmaxf(mm, sw[r2]) : mm;
        float cc = exp2p(mm - mf);
        float pd = dbit ? exp2p(sw[r2] - mf) : 0.f;
        float sf = ss * cc + pd;
        float inv = (sf > 0.f) ? __fdividef(1.f, sf) : 0.f;
        size_t gbase = ((size_t)b * Lc + rowg) * Dc + h * HDc;
        #pragma unroll
        for (int nf = 0; nf < 4; nf++) {
            int col = nf * 8 + ((lane & 3) << 1);
            float sv0 = 0.f, sv1 = 0.f;
            if (dbit) {
                sv0 = __bfloat162float(svh_[gbase + col])     + __bfloat162float(svl_[gbase + col]);
                sv1 = __bfloat162float(svh_[gbase + col + 1]) + __bfloat162float(svl_[gbase + col + 1]);
            }
            float v0 = (acc[nf][r2 * 2 + 0] * cc + pd * sv0) * inv;
            float v1 = (acc[nf][r2 * 2 + 1] * cc + pd * sv1) * inv;
            uint32_t hw = cvt2(v1, v0);
            float l0f = v0 - __int_as_float(hw << 16);
            float l1f = v1 - __int_as_float(hw & 0xffff0000u);
            *(uint32_t*)&yh_[gbase + col] = hw;
            *(uint32_t*)&yl_[gbase + col] = cvt2(l1f, l0f);
        }
    }
}

// ---------------------------------------------------------------------------
extern "C" void kernel_launch(void* const* d_in, const int* in_sizes, int n_in,
                              void* d_out, int out_size)
{
    const float* obs = (const float*)d_in[0];
    const float* act = (const float*)d_in[1];
    const int*   msk = (const int*)  d_in[2];
    const float* Wk  = (const float*)d_in[3];
    const float* bk  = (const float*)d_in[4];
    const float* Wv  = (const float*)d_in[5];
    const float* bv  = (const float*)d_in[6];
    const float* Wq  = (const float*)d_in[7];
    const float* bq  = (const float*)d_in[8];
    const float* Wks = (const float*)d_in[9];
    const float* bks = (const float*)d_in[10];
    const float* Wvs = (const float*)d_in[11];
    const float* bvs = (const float*)d_in[12];
    const float* Wp  = (const float*)d_in[13];
    const float* bp  = (const float*)d_in[14];
    float* out = (float*)d_out;

    unsigned* pmb;
    __nv_bfloat16 *paug_h, *paug_l, *pwt_h, *pwt_l;
    __nv_bfloat16 *pkh, *pkl, *pvh, *pvl, *pqh, *pql, *pskh, *pskl, *psvh, *psvl, *pyh, *pyl;
    cudaGetSymbolAddress((void**)&pmb, g_mb);
    cudaGetSymbolAddress((void**)&paug_h, g_aug_hi);
    cudaGetSymbolAddress((void**)&paug_l, g_aug_lo);
    cudaGetSymbolAddress((void**)&pwt_h,  g_wt_hi);
    cudaGetSymbolAddress((void**)&pwt_l,  g_wt_lo);
    cudaGetSymbolAddress((void**)&pkh, g_kh);   cudaGetSymbolAddress((void**)&pkl, g_kl);
    cudaGetSymbolAddress((void**)&pvh, g_vh);   cudaGetSymbolAddress((void**)&pvl, g_vl);
    cudaGetSymbolAddress((void**)&pqh, g_qh);   cudaGetSymbolAddress((void**)&pql, g_ql);
    cudaGetSymbolAddress((void**)&pskh, g_skh); cudaGetSymbolAddress((void**)&pskl, g_skl);
    cudaGetSymbolAddress((void**)&psvh, g_svh); cudaGetSymbolAddress((void**)&psvl, g_svl);
    cudaGetSymbolAddress((void**)&pyh, g_yh);   cudaGetSymbolAddress((void**)&pyl, g_yl);

    cudaFuncSetAttribute(mma_gemm_kernel,
                         cudaFuncAttributeMaxDynamicSharedMemorySize, GEMM_SMEM_BYTES);
    cudaFuncSetAttribute(attn_mma_kernel,
                         cudaFuncAttributeMaxDynamicSharedMemorySize, ATTN_SMEM_BYTES);

    pack_mask_kernel<<<(Bc*Lc*Lc)/256, 256>>>(msk, pmb);
    aug_split_kernel<<<(Mc*2*Dc)/256, 256>>>(obs, act, paug_h, paug_l);
    w_split_t_kernel<<<dim3(8,16), 256>>>(Wk,  512, pwt_h + OFF_WK,  pwt_l + OFF_WK);
    w_split_t_kernel<<<dim3(8,16), 256>>>(Wv,  512, pwt_h + OFF_WV,  pwt_l + OFF_WV);
    w_split_t_kernel<<<dim3(8,8),  256>>>(Wq,  256, pwt_h + OFF_WQ,  pwt_l + OFF_WQ);
    w_split_t_kernel<<<dim3(8,8),  256>>>(Wks, 256, pwt_h + OFF_WKS, pwt_l + OFF_WKS);
    w_split_t_kernel<<<dim3(8,8),  256>>>(Wvs, 256, pwt_h + OFF_WVS, pwt_l + OFF_WVS);
    w_split_t_kernel<<<dim3(8,8),  256>>>(Wp,  256, pwt_h + OFF_WP,  pwt_l + OFF_WP);

    const float alpha_q = 1.4426950408889634f / 5.656854249492381f; // log2(e)/sqrt(32)
    dim3 gdim(2, Mc / 128);
    mma_gemm_kernel<<<gdim, 256, GEMM_SMEM_BYTES>>>(paug_h, paug_l, 512, 512,
        pwt_h + OFF_WK,  pwt_l + OFF_WK,  bk,  1.0f,    nullptr, pkh,  pkl);
    mma_gemm_kernel<<<gdim, 256, GEMM_SMEM_BYTES>>>(paug_h, paug_l, 512, 512,
        pwt_h + OFF_WV,  pwt_l + OFF_WV,  bv,  1.0f,    nullptr, pvh,  pvl);
    mma_gemm_kernel<<<gdim, 256, GEMM_SMEM_BYTES>>>(paug_h, paug_l, 512, 256,
        pwt_h + OFF_WQ,  pwt_l + OFF_WQ,  bq,  alpha_q, nullptr, pqh,  pql);
    mma_gemm_kernel<<<gdim, 256, GEMM_SMEM_BYTES>>>(paug_h, paug_l, 512, 256,
        pwt_h + OFF_WKS, pwt_l + OFF_WKS, bks, 1.0f,    nullptr, pskh, pskl);
    mma_gemm_kernel<<<gdim, 256, GEMM_SMEM_BYTES>>>(paug_h, paug_l, 512, 256,
        pwt_h + OFF_WVS, pwt_l + OFF_WVS, bvs, 1.0f,    nullptr, psvh, psvl);

    dim3 adim(Lc / 128, Bc * Hc);   // (8, 64)
    attn_mma_kernel<<<adim, 256, ATTN_SMEM_BYTES>>>(pqh, pql, pkh, pkl, pvh, pvl,
                                                    pskh, pskl, psvh, psvl, pmb, pyh, pyl);

    mma_gemm_kernel<<<gdim, 256, GEMM_SMEM_BYTES>>>(pyh, pyl, 256, 256,
        pwt_h + OFF_WP,  pwt_l + OFF_WP,  bp, 1.0f, out, nullptr, nullptr);
}